// round 1
// baseline (speedup 1.0000x reference)
#include <cuda_runtime.h>
#include <cstdint>

#define N_NODES_C  100000
#define N_EDGES_C  1600000
#define CH         128
#define N_GRAPHS_C 256

// ---------------- scratch (static device globals; no allocation) ----------------
__device__ float g_bufA[(size_t)N_NODES_C * CH];   // 51.2 MB
__device__ float g_bufB[(size_t)N_NODES_C * CH];   // 51.2 MB
__device__ float g_deg[N_NODES_C];
__device__ float g_dis[N_NODES_C];                 // deg^-0.5
__device__ float g_invdeg[N_NODES_C];              // 1/deg
__device__ float g_gsum[N_GRAPHS_C];
__device__ float g_gcnt[N_GRAPHS_C];

// ---------------- degree ----------------
__global__ void deg_init_kernel() {
    int i = blockIdx.x * blockDim.x + threadIdx.x;
    if (i < N_NODES_C) g_deg[i] = 1.0f;   // self-loop
}

__global__ void deg_count_kernel(const int* __restrict__ dst) {
    int e = blockIdx.x * blockDim.x + threadIdx.x;
    if (e < N_EDGES_C) atomicAdd(&g_deg[dst[e]], 1.0f);
}

__global__ void deg_finalize_kernel() {
    int i = blockIdx.x * blockDim.x + threadIdx.x;
    if (i < N_NODES_C) {
        float d = g_deg[i];
        g_dis[i]    = rsqrtf(d);
        g_invdeg[i] = 1.0f / d;
    }
}

// ---------------- SGEMM: Y[M,128] = X[M,128] @ W[128,128] ----------------
// Block: 256 threads, 128 rows per block, 8x8 micro-tile per thread.
__global__ __launch_bounds__(256) void gemm128_kernel(
    const float* __restrict__ X, const float* __restrict__ W,
    float* __restrict__ Y, int M)
{
    __shared__ float sX[128 * 32];   // 16 KB
    __shared__ float sW[32 * 128];   // 16 KB

    const int tid = threadIdx.x;
    const int tx  = tid & 15;        // col group (8 cols each)
    const int ty  = tid >> 4;        // row group (8 rows each)
    const int rowBase = blockIdx.x * 128;

    float acc[8][8];
    #pragma unroll
    for (int i = 0; i < 8; i++)
        #pragma unroll
        for (int j = 0; j < 8; j++) acc[i][j] = 0.0f;

    for (int kc = 0; kc < 4; kc++) {
        // load X tile: 128 rows x 32 k
        #pragma unroll
        for (int v = 0; v < 4; v++) {
            int fi = tid + v * 256;          // float4 id, 0..1023
            int r  = fi >> 3;                // 8 float4 per row
            int k4 = fi & 7;
            float4 val = make_float4(0.f, 0.f, 0.f, 0.f);
            int gr = rowBase + r;
            if (gr < M)
                val = *(const float4*)(X + (size_t)gr * CH + kc * 32 + k4 * 4);
            *(float4*)(sX + r * 32 + k4 * 4) = val;
        }
        // load W tile: 32 k x 128 n
        #pragma unroll
        for (int v = 0; v < 4; v++) {
            int fi = tid + v * 256;
            int k  = fi >> 5;                // 32 float4 per row
            int n4 = fi & 31;
            *(float4*)(sW + k * CH + n4 * 4) =
                *(const float4*)(W + (size_t)(kc * 32 + k) * CH + n4 * 4);
        }
        __syncthreads();

        #pragma unroll
        for (int k = 0; k < 32; k++) {
            float a[8], b[8];
            #pragma unroll
            for (int i = 0; i < 8; i++) a[i] = sX[(ty * 8 + i) * 32 + k];
            float4 b0 = *(const float4*)(sW + k * CH + tx * 8);
            float4 b1 = *(const float4*)(sW + k * CH + tx * 8 + 4);
            b[0]=b0.x; b[1]=b0.y; b[2]=b0.z; b[3]=b0.w;
            b[4]=b1.x; b[5]=b1.y; b[6]=b1.z; b[7]=b1.w;
            #pragma unroll
            for (int i = 0; i < 8; i++)
                #pragma unroll
                for (int j = 0; j < 8; j++)
                    acc[i][j] += a[i] * b[j];
        }
        __syncthreads();
    }

    #pragma unroll
    for (int i = 0; i < 8; i++) {
        int gr = rowBase + ty * 8 + i;
        if (gr < M) {
            float4 o0 = make_float4(acc[i][0], acc[i][1], acc[i][2], acc[i][3]);
            float4 o1 = make_float4(acc[i][4], acc[i][5], acc[i][6], acc[i][7]);
            *(float4*)(Y + (size_t)gr * CH + tx * 8)     = o0;
            *(float4*)(Y + (size_t)gr * CH + tx * 8 + 4) = o1;
        }
    }
}

// ---------------- zero a float buffer (float4 granularity) ----------------
__global__ void zero_buf_kernel(float4* __restrict__ p, int n4) {
    int i = blockIdx.x * blockDim.x + threadIdx.x;
    if (i < n4) p[i] = make_float4(0.f, 0.f, 0.f, 0.f);
}

__global__ void zero_pool_kernel() {
    int i = threadIdx.x;
    if (i < N_GRAPHS_C) { g_gsum[i] = 0.f; g_gcnt[i] = 0.f; }
}

// ---------------- edge scatter: AGG[dst] += H[src] * dis[src]*dis[dst] ----------------
// One warp per edge; each lane handles 4 channels via a v4 reduction.
__global__ __launch_bounds__(256) void scatter_kernel(
    const int* __restrict__ src, const int* __restrict__ dst,
    const float* __restrict__ H, float* __restrict__ AGG)
{
    int warp = (blockIdx.x * blockDim.x + threadIdx.x) >> 5;
    int lane = threadIdx.x & 31;
    if (warp >= N_EDGES_C) return;
    int s = __ldg(src + warp);
    int d = __ldg(dst + warp);
    float coef = __ldg(&g_dis[s]) * __ldg(&g_dis[d]);
    float4 v = *(const float4*)(H + (size_t)s * CH + lane * 4);
    v.x *= coef; v.y *= coef; v.z *= coef; v.w *= coef;
    float* p = AGG + (size_t)d * CH + lane * 4;
    asm volatile("red.global.add.v4.f32 [%0], {%1, %2, %3, %4};"
                 :: "l"(p), "f"(v.x), "f"(v.y), "f"(v.z), "f"(v.w)
                 : "memory");
}

// ---------------- finalize: AGG = relu(AGG + H/deg + bias) ----------------
__global__ void finalize_kernel(float* __restrict__ AGG, const float* __restrict__ H,
                                const float* __restrict__ bias)
{
    int i4 = blockIdx.x * blockDim.x + threadIdx.x;  // float4 index
    if (i4 >= N_NODES_C * (CH / 4)) return;
    int node = i4 >> 5;                 // 32 float4 per node
    int c4   = i4 & 31;
    float inv = g_invdeg[node];
    float4 a = *(const float4*)((const float*)AGG + (size_t)i4 * 4);
    float4 h = *(const float4*)(H + (size_t)i4 * 4);
    float4 b = *(const float4*)(bias + c4 * 4);
    a.x = fmaxf(a.x + h.x * inv + b.x, 0.f);
    a.y = fmaxf(a.y + h.y * inv + b.y, 0.f);
    a.z = fmaxf(a.z + h.z * inv + b.z, 0.f);
    a.w = fmaxf(a.w + h.w * inv + b.w, 0.f);
    *(float4*)(AGG + (size_t)i4 * 4) = a;
}

// ---------------- pool: per-node dot with Wfc, segment mean ----------------
__global__ __launch_bounds__(256) void pool_kernel(
    const float* __restrict__ H, const int* __restrict__ batch,
    const float* __restrict__ Wfc)
{
    int node = (blockIdx.x * blockDim.x + threadIdx.x) >> 5;
    int lane = threadIdx.x & 31;
    if (node >= N_NODES_C) return;
    float4 h = *(const float4*)(H + (size_t)node * CH + lane * 4);
    float4 w = *(const float4*)(Wfc + lane * 4);
    float s = h.x * w.x + h.y * w.y + h.z * w.z + h.w * w.w;
    #pragma unroll
    for (int o = 16; o; o >>= 1) s += __shfl_xor_sync(0xFFFFFFFFu, s, o);
    if (lane == 0) {
        int g = __ldg(batch + node);
        atomicAdd(&g_gsum[g], s);
        atomicAdd(&g_gcnt[g], 1.0f);
    }
}

__global__ void final_out_kernel(float* __restrict__ out, const float* __restrict__ bfc) {
    int g = threadIdx.x;
    if (g < N_GRAPHS_C)
        out[g] = g_gsum[g] / fmaxf(g_gcnt[g], 1.0f) + bfc[0];
}

// ---------------- launch ----------------
extern "C" void kernel_launch(void* const* d_in, const int* in_sizes, int n_in,
                              void* d_out, int out_size)
{
    const float* x    = (const float*)d_in[0];
    const int*   edge = (const int*)  d_in[1];
    const int*   batch= (const int*)  d_in[2];
    const float* W1   = (const float*)d_in[3];
    const float* b1   = (const float*)d_in[4];
    const float* W2   = (const float*)d_in[5];
    const float* b2   = (const float*)d_in[6];
    const float* Wfc  = (const float*)d_in[7];
    const float* bfc  = (const float*)d_in[8];
    float* out = (float*)d_out;

    const int* srcp = edge;
    const int* dstp = edge + N_EDGES_C;

    float *bufA = nullptr, *bufB = nullptr;
    cudaGetSymbolAddress((void**)&bufA, g_bufA);
    cudaGetSymbolAddress((void**)&bufB, g_bufB);

    const int n4      = N_NODES_C * (CH / 4);        // 3.2M float4
    const int zgrid   = (n4 + 255) / 256;
    const int ngrid   = (N_NODES_C + 255) / 256;
    const int egrid   = (N_EDGES_C + 255) / 256;
    const int ggrid   = (N_NODES_C * 128 + 32767) / 32768; // gemm: 128 rows/block
    const int sgrid   = (N_EDGES_C + 7) / 8;         // 8 edges (warps) per block
    const int pgrid   = (N_NODES_C * 32 + 255) / 256;

    // degrees (shared across both layers)
    deg_init_kernel<<<ngrid, 256>>>();
    deg_count_kernel<<<egrid, 256>>>(dstp);
    deg_finalize_kernel<<<ngrid, 256>>>();

    // ---- layer 1 ----
    gemm128_kernel<<<(N_NODES_C + 127) / 128, 256>>>(x, W1, bufA, N_NODES_C);
    zero_buf_kernel<<<zgrid, 256>>>((float4*)bufB, n4);
    scatter_kernel<<<sgrid, 256>>>(srcp, dstp, bufA, bufB);
    finalize_kernel<<<zgrid, 256>>>(bufB, bufA, b1);

    // ---- layer 2 ----
    gemm128_kernel<<<(N_NODES_C + 127) / 128, 256>>>(bufB, W2, bufA, N_NODES_C);
    zero_buf_kernel<<<zgrid, 256>>>((float4*)bufB, n4);
    scatter_kernel<<<sgrid, 256>>>(srcp, dstp, bufA, bufB);
    finalize_kernel<<<zgrid, 256>>>(bufB, bufA, b2);

    // ---- pool + fc ----
    zero_pool_kernel<<<1, 256>>>();
    pool_kernel<<<pgrid, 256>>>(bufB, batch, Wfc);
    final_out_kernel<<<1, 256>>>(out, bfc);

    (void)in_sizes; (void)n_in; (void)out_size; (void)ggrid;
}

// round 2
// speedup vs baseline: 1.2392x; 1.2392x over previous
#include <cuda_runtime.h>
#include <cstdint>

#define N_NODES_C  100000
#define N_EDGES_C  1600000
#define CH         128
#define N_GRAPHS_C 256

// ---------------- scratch (static device globals; no allocation) ----------------
__device__ float g_bufA[(size_t)N_NODES_C * CH];   // 51.2 MB  (H = X@W)
__device__ float g_bufB[(size_t)N_NODES_C * CH];   // 51.2 MB  (layer-1 output)
__device__ float g_dis[N_NODES_C];                 // deg^-0.5
__device__ float g_invdeg[N_NODES_C];              // 1/deg
__device__ int   g_cnt[N_NODES_C];                 // in-degree (edges only)
__device__ int   g_rowptr[N_NODES_C + 1];
__device__ int   g_cursor[N_NODES_C];
__device__ int   g_csr_src[N_EDGES_C];
__device__ float g_csr_coef[N_EDGES_C];
__device__ float g_gsum[N_GRAPHS_C];
__device__ float g_gcnt[N_GRAPHS_C];

// ---------------- degree / CSR build ----------------
__global__ void cnt_init_kernel() {
    int i = blockIdx.x * blockDim.x + threadIdx.x;
    if (i < N_NODES_C) g_cnt[i] = 0;
}

__global__ void cnt_count_kernel(const int* __restrict__ dst) {
    int e = blockIdx.x * blockDim.x + threadIdx.x;
    if (e < N_EDGES_C) atomicAdd(&g_cnt[dst[e]], 1);
}

// single-block exclusive scan over g_cnt -> g_rowptr / g_cursor
__global__ __launch_bounds__(1024) void scan_kernel() {
    __shared__ int ssum[1024];
    const int T = 1024;
    const int chunk = (N_NODES_C + T - 1) / T;   // 98
    int t = threadIdx.x;
    int beg = t * chunk;
    int end = min(beg + chunk, N_NODES_C);
    int local = 0;
    for (int i = beg; i < end; i++) local += g_cnt[i];
    ssum[t] = local;
    __syncthreads();
    // Hillis-Steele inclusive scan on ssum
    for (int o = 1; o < T; o <<= 1) {
        int v = (t >= o) ? ssum[t - o] : 0;
        __syncthreads();
        ssum[t] += v;
        __syncthreads();
    }
    int run = (t > 0) ? ssum[t - 1] : 0;         // exclusive prefix for this chunk
    for (int i = beg; i < end; i++) {
        int c = g_cnt[i];
        g_rowptr[i] = run;
        g_cursor[i] = run;
        run += c;
    }
    if (t == T - 1) g_rowptr[N_NODES_C] = N_EDGES_C;
}

__global__ void deg_finalize_kernel() {
    int i = blockIdx.x * blockDim.x + threadIdx.x;
    if (i < N_NODES_C) {
        float d = 1.0f + (float)g_cnt[i];        // self-loop
        g_dis[i]    = rsqrtf(d);
        g_invdeg[i] = 1.0f / d;
    }
}

__global__ void csr_fill_kernel(const int* __restrict__ src, const int* __restrict__ dst) {
    int e = blockIdx.x * blockDim.x + threadIdx.x;
    if (e >= N_EDGES_C) return;
    int s = src[e];
    int d = dst[e];
    int pos = atomicAdd(&g_cursor[d], 1);
    g_csr_src[pos]  = s;
    g_csr_coef[pos] = g_dis[s] * g_dis[d];
}

// ---------------- SGEMM: Y[M,128] = X[M,128] @ W[128,128] ----------------
__global__ __launch_bounds__(256) void gemm128_kernel(
    const float* __restrict__ X, const float* __restrict__ W,
    float* __restrict__ Y, int M)
{
    __shared__ float sX[128 * 32];
    __shared__ float sW[32 * 128];

    const int tid = threadIdx.x;
    const int tx  = tid & 15;
    const int ty  = tid >> 4;
    const int rowBase = blockIdx.x * 128;

    float acc[8][8];
    #pragma unroll
    for (int i = 0; i < 8; i++)
        #pragma unroll
        for (int j = 0; j < 8; j++) acc[i][j] = 0.0f;

    for (int kc = 0; kc < 4; kc++) {
        #pragma unroll
        for (int v = 0; v < 4; v++) {
            int fi = tid + v * 256;
            int r  = fi >> 3;
            int k4 = fi & 7;
            float4 val = make_float4(0.f, 0.f, 0.f, 0.f);
            int gr = rowBase + r;
            if (gr < M)
                val = *(const float4*)(X + (size_t)gr * CH + kc * 32 + k4 * 4);
            *(float4*)(sX + r * 32 + k4 * 4) = val;
        }
        #pragma unroll
        for (int v = 0; v < 4; v++) {
            int fi = tid + v * 256;
            int k  = fi >> 5;
            int n4 = fi & 31;
            *(float4*)(sW + k * CH + n4 * 4) =
                *(const float4*)(W + (size_t)(kc * 32 + k) * CH + n4 * 4);
        }
        __syncthreads();

        #pragma unroll
        for (int k = 0; k < 32; k++) {
            float a[8], b[8];
            #pragma unroll
            for (int i = 0; i < 8; i++) a[i] = sX[(ty * 8 + i) * 32 + k];
            float4 b0 = *(const float4*)(sW + k * CH + tx * 8);
            float4 b1 = *(const float4*)(sW + k * CH + tx * 8 + 4);
            b[0]=b0.x; b[1]=b0.y; b[2]=b0.z; b[3]=b0.w;
            b[4]=b1.x; b[5]=b1.y; b[6]=b1.z; b[7]=b1.w;
            #pragma unroll
            for (int i = 0; i < 8; i++)
                #pragma unroll
                for (int j = 0; j < 8; j++)
                    acc[i][j] += a[i] * b[j];
        }
        __syncthreads();
    }

    #pragma unroll
    for (int i = 0; i < 8; i++) {
        int gr = rowBase + ty * 8 + i;
        if (gr < M) {
            *(float4*)(Y + (size_t)gr * CH + tx * 8) =
                make_float4(acc[i][0], acc[i][1], acc[i][2], acc[i][3]);
            *(float4*)(Y + (size_t)gr * CH + tx * 8 + 4) =
                make_float4(acc[i][4], acc[i][5], acc[i][6], acc[i][7]);
        }
    }
}

// ---------------- gather aggregation ----------------
// OUT[node] = relu( sum_{e in in(node)} coef_e * H[src_e] + H[node]*invdeg + bias )
// MODE 0: write OUT.   MODE 1: no OUT write; dot with Wfc, atomicAdd into g_gsum[batch].
template <int MODE>
__global__ __launch_bounds__(256) void agg_kernel(
    const float* __restrict__ H, const float* __restrict__ bias,
    float* __restrict__ OUT,
    const float* __restrict__ Wfc, const int* __restrict__ batch)
{
    int node = (blockIdx.x * blockDim.x + threadIdx.x) >> 5;
    int lane = threadIdx.x & 31;
    if (node >= N_NODES_C) return;

    float4 b4 = *(const float4*)(bias + lane * 4);
    float4 h4 = *(const float4*)(H + (size_t)node * CH + lane * 4);
    float inv = __ldg(&g_invdeg[node]);
    float4 acc;
    acc.x = h4.x * inv + b4.x;
    acc.y = h4.y * inv + b4.y;
    acc.z = h4.z * inv + b4.z;
    acc.w = h4.w * inv + b4.w;

    int beg = __ldg(&g_rowptr[node]);
    int end = __ldg(&g_rowptr[node + 1]);

    for (int j = beg; j < end; j += 32) {
        int n = min(32, end - j);
        int   si = (lane < n) ? __ldg(&g_csr_src[j + lane])  : 0;
        float ci = (lane < n) ? __ldg(&g_csr_coef[j + lane]) : 0.0f;
        // process pairs for MLP=2
        int t = 0;
        for (; t + 2 <= n; t += 2) {
            int   s0 = __shfl_sync(0xFFFFFFFFu, si, t);
            float c0 = __shfl_sync(0xFFFFFFFFu, ci, t);
            int   s1 = __shfl_sync(0xFFFFFFFFu, si, t + 1);
            float c1 = __shfl_sync(0xFFFFFFFFu, ci, t + 1);
            float4 v0 = *(const float4*)(H + (size_t)s0 * CH + lane * 4);
            float4 v1 = *(const float4*)(H + (size_t)s1 * CH + lane * 4);
            acc.x += c0 * v0.x + c1 * v1.x;
            acc.y += c0 * v0.y + c1 * v1.y;
            acc.z += c0 * v0.z + c1 * v1.z;
            acc.w += c0 * v0.w + c1 * v1.w;
        }
        if (t < n) {
            int   s0 = __shfl_sync(0xFFFFFFFFu, si, t);
            float c0 = __shfl_sync(0xFFFFFFFFu, ci, t);
            float4 v0 = *(const float4*)(H + (size_t)s0 * CH + lane * 4);
            acc.x += c0 * v0.x;
            acc.y += c0 * v0.y;
            acc.z += c0 * v0.z;
            acc.w += c0 * v0.w;
        }
    }

    acc.x = fmaxf(acc.x, 0.f);
    acc.y = fmaxf(acc.y, 0.f);
    acc.z = fmaxf(acc.z, 0.f);
    acc.w = fmaxf(acc.w, 0.f);

    if (MODE == 0) {
        *(float4*)(OUT + (size_t)node * CH + lane * 4) = acc;
    } else {
        float4 w4 = *(const float4*)(Wfc + lane * 4);
        float s = acc.x * w4.x + acc.y * w4.y + acc.z * w4.z + acc.w * w4.w;
        #pragma unroll
        for (int o = 16; o; o >>= 1) s += __shfl_xor_sync(0xFFFFFFFFu, s, o);
        if (lane == 0) atomicAdd(&g_gsum[__ldg(batch + node)], s);
    }
}

// ---------------- pooling helpers ----------------
__global__ void zero_pool_kernel() {
    int i = threadIdx.x;
    if (i < N_GRAPHS_C) { g_gsum[i] = 0.f; g_gcnt[i] = 0.f; }
}

__global__ void graph_cnt_kernel(const int* __restrict__ batch) {
    int i = blockIdx.x * blockDim.x + threadIdx.x;
    if (i < N_NODES_C) atomicAdd(&g_gcnt[batch[i]], 1.0f);
}

__global__ void final_out_kernel(float* __restrict__ out, const float* __restrict__ bfc) {
    int g = threadIdx.x;
    if (g < N_GRAPHS_C)
        out[g] = g_gsum[g] / fmaxf(g_gcnt[g], 1.0f) + bfc[0];
}

// ---------------- launch ----------------
extern "C" void kernel_launch(void* const* d_in, const int* in_sizes, int n_in,
                              void* d_out, int out_size)
{
    const float* x    = (const float*)d_in[0];
    const int*   edge = (const int*)  d_in[1];
    const int*   batch= (const int*)  d_in[2];
    const float* W1   = (const float*)d_in[3];
    const float* b1   = (const float*)d_in[4];
    const float* W2   = (const float*)d_in[5];
    const float* b2   = (const float*)d_in[6];
    const float* Wfc  = (const float*)d_in[7];
    const float* bfc  = (const float*)d_in[8];
    float* out = (float*)d_out;

    const int* srcp = edge;
    const int* dstp = edge + N_EDGES_C;

    float *bufA = nullptr, *bufB = nullptr;
    cudaGetSymbolAddress((void**)&bufA, g_bufA);
    cudaGetSymbolAddress((void**)&bufB, g_bufB);

    const int ngrid = (N_NODES_C + 255) / 256;
    const int egrid = (N_EDGES_C + 255) / 256;
    const int agrid = (N_NODES_C + 7) / 8;     // 8 warps (nodes) per 256-thread block

    // ---- degree + CSR (by dst) ----
    cnt_init_kernel<<<ngrid, 256>>>();
    cnt_count_kernel<<<egrid, 256>>>(dstp);
    scan_kernel<<<1, 1024>>>();
    deg_finalize_kernel<<<ngrid, 256>>>();
    csr_fill_kernel<<<egrid, 256>>>(srcp, dstp);
    zero_pool_kernel<<<1, 256>>>();
    graph_cnt_kernel<<<ngrid, 256>>>(batch);

    // ---- layer 1 ----
    gemm128_kernel<<<(N_NODES_C + 127) / 128, 256>>>(x, W1, bufA, N_NODES_C);
    agg_kernel<0><<<agrid, 256>>>(bufA, b1, bufB, nullptr, nullptr);

    // ---- layer 2 (aggregation fused with pooled FC dot) ----
    gemm128_kernel<<<(N_NODES_C + 127) / 128, 256>>>(bufB, W2, bufA, N_NODES_C);
    agg_kernel<1><<<agrid, 256>>>(bufA, b2, nullptr, Wfc, batch);

    // ---- final ----
    final_out_kernel<<<1, 256>>>(out, bfc);

    (void)in_sizes; (void)n_in; (void)out_size;
}

// round 5
// speedup vs baseline: 1.7431x; 1.4067x over previous
#include <cuda_runtime.h>
#include <cstdint>

#define N_NODES_C  100000
#define N_EDGES_C  1600000
#define CH         128
#define N_GRAPHS_C 256
#define NBLK       ((N_NODES_C + 255) / 256)   // 391

// ---------------- scratch (static device globals; no allocation) ----------------
__device__ float g_bufA[(size_t)N_NODES_C * CH];   // 51.2 MB
__device__ float g_bufB[(size_t)N_NODES_C * CH];   // 51.2 MB
__device__ float g_dis[N_NODES_C];                 // deg^-0.5
__device__ int   g_cnt[N_NODES_C];                 // in-degree (edges only)
__device__ int   g_rowptr[N_NODES_C + 1];
__device__ int   g_cursor[N_NODES_C];
__device__ int   g_csr_src[N_EDGES_C];
__device__ int   g_bsum[512];                      // block partial sums (>=NBLK)
__device__ int   g_boff[512];                      // exclusive block offsets
__device__ float g_gsum[N_GRAPHS_C];
__device__ float g_gcnt[N_GRAPHS_C];

// ---------------- zero counters (plain kernel; no host memset APIs) ----------------
__global__ void zero_counters_kernel() {
    int i = blockIdx.x * blockDim.x + threadIdx.x;
    if (i < N_NODES_C) g_cnt[i] = 0;
    if (i < N_GRAPHS_C) { g_gsum[i] = 0.f; g_gcnt[i] = 0.f; }
}

// ---------------- degree count (2 edges / thread, vectorized) ----------------
__global__ void cnt_count_kernel(const int* __restrict__ dst) {
    int i = blockIdx.x * blockDim.x + threadIdx.x;
    if (i * 2 + 1 < N_EDGES_C) {
        int2 d = *(const int2*)(dst + i * 2);
        atomicAdd(&g_cnt[d.x], 1);
        atomicAdd(&g_cnt[d.y], 1);
    } else if (i * 2 < N_EDGES_C) {
        atomicAdd(&g_cnt[dst[i * 2]], 1);
    }
}

// ---------------- 3-phase parallel scan ----------------
__global__ void partial_sum_kernel() {
    __shared__ int s[256];
    int i = blockIdx.x * 256 + threadIdx.x;
    s[threadIdx.x] = (i < N_NODES_C) ? g_cnt[i] : 0;
    __syncthreads();
    for (int o = 128; o; o >>= 1) {
        if (threadIdx.x < o) s[threadIdx.x] += s[threadIdx.x + o];
        __syncthreads();
    }
    if (threadIdx.x == 0) g_bsum[blockIdx.x] = s[0];
}

__global__ __launch_bounds__(512) void scan_block_kernel() {
    __shared__ int s[512];
    int t = threadIdx.x;
    int v = (t < NBLK) ? g_bsum[t] : 0;
    s[t] = v;
    __syncthreads();
    for (int o = 1; o < 512; o <<= 1) {
        int u = (t >= o) ? s[t - o] : 0;
        __syncthreads();
        s[t] += u;
        __syncthreads();
    }
    g_boff[t] = s[t] - v;    // exclusive
}

// per-block rescan + rowptr/cursor + dis (fused degree finalize)
__global__ void rowptr_fill_kernel() {
    __shared__ int s[256];
    int t = threadIdx.x;
    int i = blockIdx.x * 256 + t;
    int c = (i < N_NODES_C) ? g_cnt[i] : 0;
    s[t] = c;
    __syncthreads();
    for (int o = 1; o < 256; o <<= 1) {
        int u = (t >= o) ? s[t - o] : 0;
        __syncthreads();
        s[t] += u;
        __syncthreads();
    }
    if (i < N_NODES_C) {
        int pos = g_boff[blockIdx.x] + s[t] - c;   // exclusive prefix
        g_rowptr[i] = pos;
        g_cursor[i] = pos;
        g_dis[i] = rsqrtf(1.0f + (float)c);
    }
    if (blockIdx.x == 0 && t == 0) g_rowptr[N_NODES_C] = N_EDGES_C;
}

__global__ void csr_fill_kernel(const int* __restrict__ src, const int* __restrict__ dst) {
    int i = blockIdx.x * blockDim.x + threadIdx.x;
    if (i * 2 + 1 < N_EDGES_C) {
        int2 s = *(const int2*)(src + i * 2);
        int2 d = *(const int2*)(dst + i * 2);
        g_csr_src[atomicAdd(&g_cursor[d.x], 1)] = s.x;
        g_csr_src[atomicAdd(&g_cursor[d.y], 1)] = s.y;
    } else if (i * 2 < N_EDGES_C) {
        g_csr_src[atomicAdd(&g_cursor[dst[i * 2]], 1)] = src[i * 2];
    }
}

// ---------------- SGEMM: Y[r,:] = (X[r,:] @ W) * scale[r]   (scale nullable) ----------------
__global__ __launch_bounds__(256, 2) void gemm128_kernel(
    const float* __restrict__ X, const float* __restrict__ W,
    float* __restrict__ Y, const float* __restrict__ scale, int M)
{
    __shared__ float sX[128 * 32];
    __shared__ float sW[32 * 128];

    const int tid = threadIdx.x;
    const int tx  = tid & 15;
    const int ty  = tid >> 4;
    const int rowBase = blockIdx.x * 128;

    float acc[8][8];
    #pragma unroll
    for (int i = 0; i < 8; i++)
        #pragma unroll
        for (int j = 0; j < 8; j++) acc[i][j] = 0.0f;

    for (int kc = 0; kc < 4; kc++) {
        #pragma unroll
        for (int v = 0; v < 4; v++) {
            int fi = tid + v * 256;
            int r  = fi >> 3;
            int k4 = fi & 7;
            float4 val = make_float4(0.f, 0.f, 0.f, 0.f);
            int gr = rowBase + r;
            if (gr < M)
                val = *(const float4*)(X + (size_t)gr * CH + kc * 32 + k4 * 4);
            *(float4*)(sX + r * 32 + k4 * 4) = val;
        }
        #pragma unroll
        for (int v = 0; v < 4; v++) {
            int fi = tid + v * 256;
            int k  = fi >> 5;
            int n4 = fi & 31;
            *(float4*)(sW + k * CH + n4 * 4) =
                *(const float4*)(W + (size_t)(kc * 32 + k) * CH + n4 * 4);
        }
        __syncthreads();

        #pragma unroll
        for (int k = 0; k < 32; k++) {
            float a[8], b[8];
            #pragma unroll
            for (int i = 0; i < 8; i++) a[i] = sX[(ty * 8 + i) * 32 + k];
            float4 b0 = *(const float4*)(sW + k * CH + tx * 8);
            float4 b1 = *(const float4*)(sW + k * CH + tx * 8 + 4);
            b[0]=b0.x; b[1]=b0.y; b[2]=b0.z; b[3]=b0.w;
            b[4]=b1.x; b[5]=b1.y; b[6]=b1.z; b[7]=b1.w;
            #pragma unroll
            for (int i = 0; i < 8; i++)
                #pragma unroll
                for (int j = 0; j < 8; j++)
                    acc[i][j] += a[i] * b[j];
        }
        __syncthreads();
    }

    #pragma unroll
    for (int i = 0; i < 8; i++) {
        int gr = rowBase + ty * 8 + i;
        if (gr < M) {
            float s = scale ? scale[gr] : 1.0f;
            *(float4*)(Y + (size_t)gr * CH + tx * 8) =
                make_float4(acc[i][0]*s, acc[i][1]*s, acc[i][2]*s, acc[i][3]*s);
            *(float4*)(Y + (size_t)gr * CH + tx * 8 + 4) =
                make_float4(acc[i][4]*s, acc[i][5]*s, acc[i][6]*s, acc[i][7]*s);
        }
    }
}

// ---------------- gather aggregation (Hs rows already scaled by dis[row]) ----------------
// result(node) = relu( dis[node] * (Hs[node] + sum_{e in in(node)} Hs[src_e]) + bias )
// MODE 0: write OUT.   MODE 1: dot with Wfc, atomicAdd into g_gsum[batch].
template <int MODE>
__global__ __launch_bounds__(256) void agg_kernel(
    const float* __restrict__ Hs, const float* __restrict__ bias,
    float* __restrict__ OUT,
    const float* __restrict__ Wfc, const int* __restrict__ batch)
{
    int node = (blockIdx.x * blockDim.x + threadIdx.x) >> 5;
    int lane = threadIdx.x & 31;
    if (node >= N_NODES_C) return;

    float4 acc = *(const float4*)(Hs + (size_t)node * CH + lane * 4);  // self term

    int beg = __ldg(&g_rowptr[node]);
    int end = __ldg(&g_rowptr[node + 1]);

    for (int j = beg; j < end; j += 32) {
        int n = min(32, end - j);
        int si = (lane < n) ? __ldg(&g_csr_src[j + lane]) : 0;
        int t = 0;
        for (; t + 4 <= n; t += 4) {
            int s0 = __shfl_sync(0xFFFFFFFFu, si, t);
            int s1 = __shfl_sync(0xFFFFFFFFu, si, t + 1);
            int s2 = __shfl_sync(0xFFFFFFFFu, si, t + 2);
            int s3 = __shfl_sync(0xFFFFFFFFu, si, t + 3);
            float4 v0 = *(const float4*)(Hs + (size_t)s0 * CH + lane * 4);
            float4 v1 = *(const float4*)(Hs + (size_t)s1 * CH + lane * 4);
            float4 v2 = *(const float4*)(Hs + (size_t)s2 * CH + lane * 4);
            float4 v3 = *(const float4*)(Hs + (size_t)s3 * CH + lane * 4);
            acc.x += v0.x + v1.x + v2.x + v3.x;
            acc.y += v0.y + v1.y + v2.y + v3.y;
            acc.z += v0.z + v1.z + v2.z + v3.z;
            acc.w += v0.w + v1.w + v2.w + v3.w;
        }
        for (; t < n; t++) {
            int s0 = __shfl_sync(0xFFFFFFFFu, si, t);
            float4 v0 = *(const float4*)(Hs + (size_t)s0 * CH + lane * 4);
            acc.x += v0.x; acc.y += v0.y; acc.z += v0.z; acc.w += v0.w;
        }
    }

    float dd = __ldg(&g_dis[node]);
    float4 b4 = *(const float4*)(bias + lane * 4);
    acc.x = fmaxf(acc.x * dd + b4.x, 0.f);
    acc.y = fmaxf(acc.y * dd + b4.y, 0.f);
    acc.z = fmaxf(acc.z * dd + b4.z, 0.f);
    acc.w = fmaxf(acc.w * dd + b4.w, 0.f);

    if (MODE == 0) {
        *(float4*)(OUT + (size_t)node * CH + lane * 4) = acc;
    } else {
        float4 w4 = *(const float4*)(Wfc + lane * 4);
        float s = acc.x * w4.x + acc.y * w4.y + acc.z * w4.z + acc.w * w4.w;
        #pragma unroll
        for (int o = 16; o; o >>= 1) s += __shfl_xor_sync(0xFFFFFFFFu, s, o);
        if (lane == 0) atomicAdd(&g_gsum[__ldg(batch + node)], s);
    }
}

// ---------------- pooling helpers ----------------
__global__ void graph_cnt_kernel(const int* __restrict__ batch) {
    int i = blockIdx.x * blockDim.x + threadIdx.x;
    if (i < N_NODES_C) atomicAdd(&g_gcnt[batch[i]], 1.0f);
}

__global__ void final_out_kernel(float* __restrict__ out, const float* __restrict__ bfc) {
    int g = threadIdx.x;
    if (g < N_GRAPHS_C)
        out[g] = g_gsum[g] / fmaxf(g_gcnt[g], 1.0f) + bfc[0];
}

// ---------------- launch ----------------
extern "C" void kernel_launch(void* const* d_in, const int* in_sizes, int n_in,
                              void* d_out, int out_size)
{
    const float* x    = (const float*)d_in[0];
    const int*   edge = (const int*)  d_in[1];
    const int*   batch= (const int*)  d_in[2];
    const float* W1   = (const float*)d_in[3];
    const float* b1   = (const float*)d_in[4];
    const float* W2   = (const float*)d_in[5];
    const float* b2   = (const float*)d_in[6];
    const float* Wfc  = (const float*)d_in[7];
    const float* bfc  = (const float*)d_in[8];
    float* out = (float*)d_out;

    const int* srcp = edge;
    const int* dstp = edge + N_EDGES_C;

    float *bufA = nullptr, *bufB = nullptr, *disp = nullptr;
    cudaGetSymbolAddress((void**)&bufA, g_bufA);
    cudaGetSymbolAddress((void**)&bufB, g_bufB);
    cudaGetSymbolAddress((void**)&disp, g_dis);

    const int ngrid  = NBLK;
    const int e2grid = (N_EDGES_C / 2 + 255) / 256;
    const int agrid  = (N_NODES_C + 7) / 8;

    // ---- zero counters (plain kernel launch; capture-safe) ----
    zero_counters_kernel<<<ngrid, 256>>>();

    // ---- degree + CSR (by dst) ----
    cnt_count_kernel<<<e2grid, 256>>>(dstp);
    partial_sum_kernel<<<ngrid, 256>>>();
    scan_block_kernel<<<1, 512>>>();
    rowptr_fill_kernel<<<ngrid, 256>>>();
    csr_fill_kernel<<<e2grid, 256>>>(srcp, dstp);
    graph_cnt_kernel<<<ngrid, 256>>>(batch);

    // ---- layer 1:  Hs = (X@W1)*dis  -> gather -> relu(+b1) ----
    gemm128_kernel<<<(N_NODES_C + 127) / 128, 256>>>(x, W1, bufA, disp, N_NODES_C);
    agg_kernel<0><<<agrid, 256>>>(bufA, b1, bufB, nullptr, nullptr);

    // ---- layer 2:  Hs = (h1@W2)*dis -> gather -> relu(+b2) -> pooled FC dot ----
    gemm128_kernel<<<(N_NODES_C + 127) / 128, 256>>>(bufB, W2, bufA, disp, N_NODES_C);
    agg_kernel<1><<<agrid, 256>>>(bufA, b2, nullptr, Wfc, batch);

    // ---- final ----
    final_out_kernel<<<1, 256>>>(out, bfc);

    (void)in_sizes; (void)n_in; (void)out_size;
}

// round 7
// speedup vs baseline: 2.1886x; 1.2555x over previous
#include <cuda_runtime.h>
#include <cstdint>

#define N_NODES_C  100000
#define N_EDGES_C  1600000
#define CH         128
#define N_GRAPHS_C 256
#define NBLK       ((N_NODES_C + 255) / 256)   // 391

// ---------------- scratch (static device globals; no allocation) ----------------
__device__ float g_bufA[(size_t)N_NODES_C * CH];   // 51.2 MB
__device__ float g_bufB[(size_t)N_NODES_C * CH];   // 51.2 MB
__device__ float g_dis[N_NODES_C];                 // deg^-0.5
__device__ int   g_cnt[N_NODES_C];                 // in-degree (edges only)
__device__ int   g_rowptr[N_NODES_C + 1];
__device__ int   g_cursor[N_NODES_C];
__device__ int   g_csr_src[N_EDGES_C];
__device__ int   g_bsum[512];                      // block partial sums (>=NBLK)
__device__ int   g_boff[512];                      // exclusive block offsets
__device__ float g_gsum[N_GRAPHS_C];
__device__ float g_gcnt[N_GRAPHS_C];

// ---------------- zero counters (plain kernel; no host memset APIs) ----------------
__global__ void zero_counters_kernel() {
    int i = blockIdx.x * blockDim.x + threadIdx.x;
    if (i < N_NODES_C) g_cnt[i] = 0;
    if (i < N_GRAPHS_C) { g_gsum[i] = 0.f; g_gcnt[i] = 0.f; }
}

// ---------------- degree count (2 edges / thread, vectorized) ----------------
__global__ void cnt_count_kernel(const int* __restrict__ dst) {
    int i = blockIdx.x * blockDim.x + threadIdx.x;
    if (i * 2 + 1 < N_EDGES_C) {
        int2 d = *(const int2*)(dst + i * 2);
        atomicAdd(&g_cnt[d.x], 1);
        atomicAdd(&g_cnt[d.y], 1);
    } else if (i * 2 < N_EDGES_C) {
        atomicAdd(&g_cnt[dst[i * 2]], 1);
    }
}

// ---------------- 3-phase parallel scan ----------------
__global__ void partial_sum_kernel() {
    __shared__ int s[256];
    int i = blockIdx.x * 256 + threadIdx.x;
    s[threadIdx.x] = (i < N_NODES_C) ? g_cnt[i] : 0;
    __syncthreads();
    for (int o = 128; o; o >>= 1) {
        if (threadIdx.x < o) s[threadIdx.x] += s[threadIdx.x + o];
        __syncthreads();
    }
    if (threadIdx.x == 0) g_bsum[blockIdx.x] = s[0];
}

__global__ __launch_bounds__(512) void scan_block_kernel() {
    __shared__ int s[512];
    int t = threadIdx.x;
    int v = (t < NBLK) ? g_bsum[t] : 0;
    s[t] = v;
    __syncthreads();
    for (int o = 1; o < 512; o <<= 1) {
        int u = (t >= o) ? s[t - o] : 0;
        __syncthreads();
        s[t] += u;
        __syncthreads();
    }
    g_boff[t] = s[t] - v;    // exclusive
}

// per-block rescan + rowptr/cursor + dis (fused degree finalize)
__global__ void rowptr_fill_kernel() {
    __shared__ int s[256];
    int t = threadIdx.x;
    int i = blockIdx.x * 256 + t;
    int c = (i < N_NODES_C) ? g_cnt[i] : 0;
    s[t] = c;
    __syncthreads();
    for (int o = 1; o < 256; o <<= 1) {
        int u = (t >= o) ? s[t - o] : 0;
        __syncthreads();
        s[t] += u;
        __syncthreads();
    }
    if (i < N_NODES_C) {
        int pos = g_boff[blockIdx.x] + s[t] - c;   // exclusive prefix
        g_rowptr[i] = pos;
        g_cursor[i] = pos;
        g_dis[i] = rsqrtf(1.0f + (float)c);
    }
    if (blockIdx.x == 0 && t == 0) g_rowptr[N_NODES_C] = N_EDGES_C;
}

__global__ void csr_fill_kernel(const int* __restrict__ src, const int* __restrict__ dst) {
    int i = blockIdx.x * blockDim.x + threadIdx.x;
    if (i * 2 + 1 < N_EDGES_C) {
        int2 s = *(const int2*)(src + i * 2);
        int2 d = *(const int2*)(dst + i * 2);
        g_csr_src[atomicAdd(&g_cursor[d.x], 1)] = s.x;
        g_csr_src[atomicAdd(&g_cursor[d.y], 1)] = s.y;
    } else if (i * 2 < N_EDGES_C) {
        g_csr_src[atomicAdd(&g_cursor[dst[i * 2]], 1)] = src[i * 2];
    }
}

// ---------------- tf32 tensor-core GEMM: Y[r,:] = (X[r,:] @ W) * scale[r] ----------------
// 256 threads (8 warps), 128 rows per block, full K=128, N in two 64-col halves.
// A fragments in registers (loaded direct from global); W half staged in 32KB static smem.
__device__ __forceinline__ uint32_t f2tf32(float v) {
    uint32_t t;
    asm("cvt.rna.tf32.f32 %0, %1;" : "=r"(t) : "f"(v));
    return t;
}

__global__ __launch_bounds__(256) void gemm_tf32_kernel(
    const float* __restrict__ X, const float* __restrict__ W,
    float* __restrict__ Y, const float* __restrict__ scale, int M)
{
    __shared__ uint32_t sB[8192];            // 32 KB: one N-half of W, fragment-packed

    const int tid  = threadIdx.x;
    const int warp = tid >> 5;
    const int lane = tid & 31;
    const int gid  = lane >> 2;              // groupID 0..7
    const int tig  = lane & 3;               // threadID_in_group 0..3
    const int rowBase = blockIdx.x * 128;

    const int r0 = rowBase + warp * 16 + gid;   // this thread's two A rows
    const int r1 = r0 + 8;
    const bool v0 = (r0 < M);
    const bool v1 = (r1 < M);
    const float* X0 = X + (size_t)r0 * CH;
    const float* X1 = X + (size_t)r1 * CH;

    // ---- A fragments in registers: a[kk][0..3], tf32 ----
    uint32_t a[16][4];
    #pragma unroll
    for (int kk = 0; kk < 16; kk++) {
        int c0 = kk * 8 + tig;
        a[kk][0] = v0 ? f2tf32(__ldg(X0 + c0))     : 0u;
        a[kk][1] = v1 ? f2tf32(__ldg(X1 + c0))     : 0u;
        a[kk][2] = v0 ? f2tf32(__ldg(X0 + c0 + 4)) : 0u;
        a[kk][3] = v1 ? f2tf32(__ldg(X1 + c0 + 4)) : 0u;
    }

    float acc[16][4];
    #pragma unroll
    for (int nt = 0; nt < 16; nt++)
        #pragma unroll
        for (int j = 0; j < 4; j++) acc[nt][j] = 0.f;

    // ---- two N-halves ----
    #pragma unroll
    for (int h = 0; h < 2; h++) {
        // pack W[:, h*64 .. h*64+63] fragments:
        // idx = kk*512 + nt'*64 + lane_*2 + half
        // k = kk*8 + (lane_&3) + half*4 ; n = h*64 + nt'*8 + (lane_>>2)
        #pragma unroll
        for (int v = 0; v < 32; v++) {
            int idx   = tid + v * 256;
            int half  = idx & 1;
            int lane_ = (idx >> 1) & 31;
            int ntp   = (idx >> 6) & 7;
            int kk    = idx >> 9;
            int k = kk * 8 + (lane_ & 3) + half * 4;
            int n = h * 64 + ntp * 8 + (lane_ >> 2);
            sB[idx] = f2tf32(__ldg(W + (size_t)k * CH + n));
        }
        __syncthreads();

        #pragma unroll
        for (int kk = 0; kk < 16; kk++) {
            #pragma unroll
            for (int ntp = 0; ntp < 8; ntp++) {
                uint2 b = *(const uint2*)(sB + (kk * 8 + ntp) * 64 + lane * 2);
                float* c = acc[h * 8 + ntp];
                asm volatile(
                    "mma.sync.aligned.m16n8k8.row.col.f32.tf32.tf32.f32 "
                    "{%0,%1,%2,%3}, {%4,%5,%6,%7}, {%8,%9}, {%0,%1,%2,%3};"
                    : "+f"(c[0]), "+f"(c[1]), "+f"(c[2]), "+f"(c[3])
                    : "r"(a[kk][0]), "r"(a[kk][1]), "r"(a[kk][2]), "r"(a[kk][3]),
                      "r"(b.x), "r"(b.y));
            }
        }
        __syncthreads();
    }

    // ---- epilogue: scale rows by dis[row], store ----
    float s0 = v0 ? scale[r0] : 0.f;
    float s1 = v1 ? scale[r1] : 0.f;
    #pragma unroll
    for (int nt = 0; nt < 16; nt++) {
        int col = nt * 8 + tig * 2;
        if (v0)
            *(float2*)(Y + (size_t)r0 * CH + col) =
                make_float2(acc[nt][0] * s0, acc[nt][1] * s0);
        if (v1)
            *(float2*)(Y + (size_t)r1 * CH + col) =
                make_float2(acc[nt][2] * s1, acc[nt][3] * s1);
    }
}

// ---------------- gather aggregation (Hs rows already scaled by dis[row]) ----------------
// result(node) = relu( dis[node] * (Hs[node] + sum_{e in in(node)} Hs[src_e]) + bias )
// MODE 0: write OUT.   MODE 1: dot with Wfc, atomicAdd into g_gsum[batch].
template <int MODE>
__global__ __launch_bounds__(256) void agg_kernel(
    const float* __restrict__ Hs, const float* __restrict__ bias,
    float* __restrict__ OUT,
    const float* __restrict__ Wfc, const int* __restrict__ batch)
{
    int node = (blockIdx.x * blockDim.x + threadIdx.x) >> 5;
    int lane = threadIdx.x & 31;
    if (node >= N_NODES_C) return;

    float4 acc = *(const float4*)(Hs + (size_t)node * CH + lane * 4);  // self term

    int beg = __ldg(&g_rowptr[node]);
    int end = __ldg(&g_rowptr[node + 1]);

    for (int j = beg; j < end; j += 32) {
        int n = min(32, end - j);
        int si = (lane < n) ? __ldg(&g_csr_src[j + lane]) : 0;
        int t = 0;
        for (; t + 4 <= n; t += 4) {
            int s0 = __shfl_sync(0xFFFFFFFFu, si, t);
            int s1 = __shfl_sync(0xFFFFFFFFu, si, t + 1);
            int s2 = __shfl_sync(0xFFFFFFFFu, si, t + 2);
            int s3 = __shfl_sync(0xFFFFFFFFu, si, t + 3);
            float4 v0 = *(const float4*)(Hs + (size_t)s0 * CH + lane * 4);
            float4 v1 = *(const float4*)(Hs + (size_t)s1 * CH + lane * 4);
            float4 v2 = *(const float4*)(Hs + (size_t)s2 * CH + lane * 4);
            float4 v3 = *(const float4*)(Hs + (size_t)s3 * CH + lane * 4);
            acc.x += v0.x + v1.x + v2.x + v3.x;
            acc.y += v0.y + v1.y + v2.y + v3.y;
            acc.z += v0.z + v1.z + v2.z + v3.z;
            acc.w += v0.w + v1.w + v2.w + v3.w;
        }
        for (; t < n; t++) {
            int s0 = __shfl_sync(0xFFFFFFFFu, si, t);
            float4 v0 = *(const float4*)(Hs + (size_t)s0 * CH + lane * 4);
            acc.x += v0.x; acc.y += v0.y; acc.z += v0.z; acc.w += v0.w;
        }
    }

    float dd = __ldg(&g_dis[node]);
    float4 b4 = *(const float4*)(bias + lane * 4);
    acc.x = fmaxf(acc.x * dd + b4.x, 0.f);
    acc.y = fmaxf(acc.y * dd + b4.y, 0.f);
    acc.z = fmaxf(acc.z * dd + b4.z, 0.f);
    acc.w = fmaxf(acc.w * dd + b4.w, 0.f);

    if (MODE == 0) {
        *(float4*)(OUT + (size_t)node * CH + lane * 4) = acc;
    } else {
        float4 w4 = *(const float4*)(Wfc + lane * 4);
        float s = acc.x * w4.x + acc.y * w4.y + acc.z * w4.z + acc.w * w4.w;
        #pragma unroll
        for (int o = 16; o; o >>= 1) s += __shfl_xor_sync(0xFFFFFFFFu, s, o);
        if (lane == 0) atomicAdd(&g_gsum[__ldg(batch + node)], s);
    }
}

// ---------------- pooling helpers ----------------
__global__ void graph_cnt_kernel(const int* __restrict__ batch) {
    int i = blockIdx.x * blockDim.x + threadIdx.x;
    if (i < N_NODES_C) atomicAdd(&g_gcnt[batch[i]], 1.0f);
}

__global__ void final_out_kernel(float* __restrict__ out, const float* __restrict__ bfc) {
    int g = threadIdx.x;
    if (g < N_GRAPHS_C)
        out[g] = g_gsum[g] / fmaxf(g_gcnt[g], 1.0f) + bfc[0];
}

// ---------------- launch ----------------
extern "C" void kernel_launch(void* const* d_in, const int* in_sizes, int n_in,
                              void* d_out, int out_size)
{
    const float* x    = (const float*)d_in[0];
    const int*   edge = (const int*)  d_in[1];
    const int*   batch= (const int*)  d_in[2];
    const float* W1   = (const float*)d_in[3];
    const float* b1   = (const float*)d_in[4];
    const float* W2   = (const float*)d_in[5];
    const float* b2   = (const float*)d_in[6];
    const float* Wfc  = (const float*)d_in[7];
    const float* bfc  = (const float*)d_in[8];
    float* out = (float*)d_out;

    const int* srcp = edge;
    const int* dstp = edge + N_EDGES_C;

    float *bufA = nullptr, *bufB = nullptr, *disp = nullptr;
    cudaGetSymbolAddress((void**)&bufA, g_bufA);
    cudaGetSymbolAddress((void**)&bufB, g_bufB);
    cudaGetSymbolAddress((void**)&disp, g_dis);

    const int ngrid  = NBLK;
    const int e2grid = (N_EDGES_C / 2 + 255) / 256;
    const int agrid  = (N_NODES_C + 7) / 8;
    const int ggrid  = (N_NODES_C + 127) / 128;

    // ---- zero counters (plain kernel launch; capture-safe) ----
    zero_counters_kernel<<<ngrid, 256>>>();

    // ---- degree + CSR (by dst) ----
    cnt_count_kernel<<<e2grid, 256>>>(dstp);
    partial_sum_kernel<<<ngrid, 256>>>();
    scan_block_kernel<<<1, 512>>>();
    rowptr_fill_kernel<<<ngrid, 256>>>();
    csr_fill_kernel<<<e2grid, 256>>>(srcp, dstp);
    graph_cnt_kernel<<<ngrid, 256>>>(batch);

    // ---- layer 1:  Hs = (X@W1)*dis  -> gather -> relu(+b1) ----
    gemm_tf32_kernel<<<ggrid, 256>>>(x, W1, bufA, disp, N_NODES_C);
    agg_kernel<0><<<agrid, 256>>>(bufA, b1, bufB, nullptr, nullptr);

    // ---- layer 2:  Hs = (h1@W2)*dis -> gather -> relu(+b2) -> pooled FC dot ----
    gemm_tf32_kernel<<<ggrid, 256>>>(bufB, W2, bufA, disp, N_NODES_C);
    agg_kernel<1><<<agrid, 256>>>(bufA, b2, nullptr, Wfc, batch);

    // ---- final ----
    final_out_kernel<<<1, 256>>>(out, bfc);

    (void)in_sizes; (void)n_in; (void)out_size;
}

// round 8
// speedup vs baseline: 2.3789x; 1.0870x over previous
#include <cuda_runtime.h>
#include <cuda_fp16.h>
#include <cstdint>

#define N_NODES_C  100000
#define N_EDGES_C  1600000
#define CH         128
#define N_GRAPHS_C 256
#define NBLK       ((N_NODES_C + 255) / 256)   // 391

// ---------------- scratch (static device globals; no allocation) ----------------
__device__ __half g_bufA[(size_t)N_NODES_C * CH];  // 25.6 MB (Hs, fp16)
__device__ __half g_bufB[(size_t)N_NODES_C * CH];  // 25.6 MB (h1, fp16)
__device__ float g_dis[N_NODES_C];                 // deg^-0.5
__device__ int   g_cnt[N_NODES_C];                 // in-degree (edges only)
__device__ int   g_rowptr[N_NODES_C + 1];
__device__ int   g_cursor[N_NODES_C];
__device__ int   g_csr_src[N_EDGES_C];
__device__ int   g_bsum[512];                      // block partial sums (>=NBLK)
__device__ int   g_boff[512];                      // exclusive block offsets
__device__ float g_gsum[N_GRAPHS_C];
__device__ float g_gcnt[N_GRAPHS_C];

// ---------------- zero counters (plain kernel; no host memset APIs) ----------------
__global__ void zero_counters_kernel() {
    int i = blockIdx.x * blockDim.x + threadIdx.x;
    if (i < N_NODES_C) g_cnt[i] = 0;
    if (i < N_GRAPHS_C) { g_gsum[i] = 0.f; g_gcnt[i] = 0.f; }
}

// ---------------- degree count (2 edges / thread, vectorized) ----------------
__global__ void cnt_count_kernel(const int* __restrict__ dst) {
    int i = blockIdx.x * blockDim.x + threadIdx.x;
    if (i * 2 + 1 < N_EDGES_C) {
        int2 d = *(const int2*)(dst + i * 2);
        atomicAdd(&g_cnt[d.x], 1);
        atomicAdd(&g_cnt[d.y], 1);
    } else if (i * 2 < N_EDGES_C) {
        atomicAdd(&g_cnt[dst[i * 2]], 1);
    }
}

// ---------------- 3-phase parallel scan ----------------
__global__ void partial_sum_kernel() {
    __shared__ int s[256];
    int i = blockIdx.x * 256 + threadIdx.x;
    s[threadIdx.x] = (i < N_NODES_C) ? g_cnt[i] : 0;
    __syncthreads();
    for (int o = 128; o; o >>= 1) {
        if (threadIdx.x < o) s[threadIdx.x] += s[threadIdx.x + o];
        __syncthreads();
    }
    if (threadIdx.x == 0) g_bsum[blockIdx.x] = s[0];
}

__global__ __launch_bounds__(512) void scan_block_kernel() {
    __shared__ int s[512];
    int t = threadIdx.x;
    int v = (t < NBLK) ? g_bsum[t] : 0;
    s[t] = v;
    __syncthreads();
    for (int o = 1; o < 512; o <<= 1) {
        int u = (t >= o) ? s[t - o] : 0;
        __syncthreads();
        s[t] += u;
        __syncthreads();
    }
    g_boff[t] = s[t] - v;    // exclusive
}

// per-block rescan + rowptr/cursor + dis (fused degree finalize)
__global__ void rowptr_fill_kernel() {
    __shared__ int s[256];
    int t = threadIdx.x;
    int i = blockIdx.x * 256 + t;
    int c = (i < N_NODES_C) ? g_cnt[i] : 0;
    s[t] = c;
    __syncthreads();
    for (int o = 1; o < 256; o <<= 1) {
        int u = (t >= o) ? s[t - o] : 0;
        __syncthreads();
        s[t] += u;
        __syncthreads();
    }
    if (i < N_NODES_C) {
        int pos = g_boff[blockIdx.x] + s[t] - c;   // exclusive prefix
        g_rowptr[i] = pos;
        g_cursor[i] = pos;
        g_dis[i] = rsqrtf(1.0f + (float)c);
    }
    if (blockIdx.x == 0 && t == 0) g_rowptr[N_NODES_C] = N_EDGES_C;
}

__global__ void csr_fill_kernel(const int* __restrict__ src, const int* __restrict__ dst) {
    int i = blockIdx.x * blockDim.x + threadIdx.x;
    if (i * 2 + 1 < N_EDGES_C) {
        int2 s = *(const int2*)(src + i * 2);
        int2 d = *(const int2*)(dst + i * 2);
        g_csr_src[atomicAdd(&g_cursor[d.x], 1)] = s.x;
        g_csr_src[atomicAdd(&g_cursor[d.y], 1)] = s.y;
    } else if (i * 2 < N_EDGES_C) {
        g_csr_src[atomicAdd(&g_cursor[dst[i * 2]], 1)] = src[i * 2];
    }
}

// ---------------- tf32 tensor-core GEMM: Y[r,:] = half((X[r,:] @ W) * scale[r]) ----------------
// 256 threads (8 warps), 128 rows per block, full K=128, N in two 64-col halves.
// A fragments in registers (direct from global); W half staged in 32KB static smem.
// Templated on input type (float for layer 1, __half for layer 2). Output fp16.
__device__ __forceinline__ uint32_t f2tf32(float v) {
    uint32_t t;
    asm("cvt.rna.tf32.f32 %0, %1;" : "=r"(t) : "f"(v));
    return t;
}
__device__ __forceinline__ float ld_as_float(const float* p)  { return __ldg(p); }
__device__ __forceinline__ float ld_as_float(const __half* p) { return __half2float(__ldg(p)); }

template <typename T>
__global__ __launch_bounds__(256) void gemm_tf32_kernel(
    const T* __restrict__ X, const float* __restrict__ W,
    __half* __restrict__ Y, const float* __restrict__ scale, int M)
{
    __shared__ uint32_t sB[8192];            // 32 KB: one N-half of W, fragment-packed

    const int tid  = threadIdx.x;
    const int warp = tid >> 5;
    const int lane = tid & 31;
    const int gid  = lane >> 2;              // groupID 0..7
    const int tig  = lane & 3;               // threadID_in_group 0..3
    const int rowBase = blockIdx.x * 128;

    const int r0 = rowBase + warp * 16 + gid;   // this thread's two A rows
    const int r1 = r0 + 8;
    const bool v0 = (r0 < M);
    const bool v1 = (r1 < M);
    const T* X0 = X + (size_t)r0 * CH;
    const T* X1 = X + (size_t)r1 * CH;

    // ---- A fragments in registers: a[kk][0..3], tf32 ----
    uint32_t a[16][4];
    #pragma unroll
    for (int kk = 0; kk < 16; kk++) {
        int c0 = kk * 8 + tig;
        a[kk][0] = v0 ? f2tf32(ld_as_float(X0 + c0))     : 0u;
        a[kk][1] = v1 ? f2tf32(ld_as_float(X1 + c0))     : 0u;
        a[kk][2] = v0 ? f2tf32(ld_as_float(X0 + c0 + 4)) : 0u;
        a[kk][3] = v1 ? f2tf32(ld_as_float(X1 + c0 + 4)) : 0u;
    }

    float acc[16][4];
    #pragma unroll
    for (int nt = 0; nt < 16; nt++)
        #pragma unroll
        for (int j = 0; j < 4; j++) acc[nt][j] = 0.f;

    // ---- two N-halves ----
    #pragma unroll
    for (int h = 0; h < 2; h++) {
        #pragma unroll
        for (int v = 0; v < 32; v++) {
            int idx   = tid + v * 256;
            int half_ = idx & 1;
            int lane_ = (idx >> 1) & 31;
            int ntp   = (idx >> 6) & 7;
            int kk    = idx >> 9;
            int k = kk * 8 + (lane_ & 3) + half_ * 4;
            int n = h * 64 + ntp * 8 + (lane_ >> 2);
            sB[idx] = f2tf32(__ldg(W + (size_t)k * CH + n));
        }
        __syncthreads();

        #pragma unroll
        for (int kk = 0; kk < 16; kk++) {
            #pragma unroll
            for (int ntp = 0; ntp < 8; ntp++) {
                uint2 b = *(const uint2*)(sB + (kk * 8 + ntp) * 64 + lane * 2);
                float* c = acc[h * 8 + ntp];
                asm volatile(
                    "mma.sync.aligned.m16n8k8.row.col.f32.tf32.tf32.f32 "
                    "{%0,%1,%2,%3}, {%4,%5,%6,%7}, {%8,%9}, {%0,%1,%2,%3};"
                    : "+f"(c[0]), "+f"(c[1]), "+f"(c[2]), "+f"(c[3])
                    : "r"(a[kk][0]), "r"(a[kk][1]), "r"(a[kk][2]), "r"(a[kk][3]),
                      "r"(b.x), "r"(b.y));
            }
        }
        __syncthreads();
    }

    // ---- epilogue: scale rows by dis[row], convert to fp16, store ----
    float s0 = v0 ? scale[r0] : 0.f;
    float s1 = v1 ? scale[r1] : 0.f;
    #pragma unroll
    for (int nt = 0; nt < 16; nt++) {
        int col = nt * 8 + tig * 2;
        if (v0)
            *(__half2*)(Y + (size_t)r0 * CH + col) =
                __floats2half2_rn(acc[nt][0] * s0, acc[nt][1] * s0);
        if (v1)
            *(__half2*)(Y + (size_t)r1 * CH + col) =
                __floats2half2_rn(acc[nt][2] * s1, acc[nt][3] * s1);
    }
}

// ---------------- gather aggregation (fp16 Hs rows pre-scaled by dis[row]) ----------------
// result(node) = relu( dis[node] * (Hs[node] + sum_{e in in(node)} Hs[src_e]) + bias )
// MODE 0: write OUT (fp16).   MODE 1: dot with Wfc, atomicAdd into g_gsum[batch].
__device__ __forceinline__ void acc_row(float4& acc, const __half* Hs, int srow, int lane) {
    uint2 raw = *(const uint2*)(Hs + (size_t)srow * CH + lane * 4);
    float2 f0 = __half22float2(*(__half2*)&raw.x);
    float2 f1 = __half22float2(*(__half2*)&raw.y);
    acc.x += f0.x; acc.y += f0.y; acc.z += f1.x; acc.w += f1.y;
}

template <int MODE>
__global__ __launch_bounds__(256) void agg_kernel(
    const __half* __restrict__ Hs, const float* __restrict__ bias,
    __half* __restrict__ OUT,
    const float* __restrict__ Wfc, const int* __restrict__ batch)
{
    int node = (blockIdx.x * blockDim.x + threadIdx.x) >> 5;
    int lane = threadIdx.x & 31;
    if (node >= N_NODES_C) return;

    float4 acc = make_float4(0.f, 0.f, 0.f, 0.f);
    acc_row(acc, Hs, node, lane);            // self term

    int beg = __ldg(&g_rowptr[node]);
    int end = __ldg(&g_rowptr[node + 1]);

    for (int j = beg; j < end; j += 32) {
        int n = min(32, end - j);
        int si = (lane < n) ? __ldg(&g_csr_src[j + lane]) : 0;
        int t = 0;
        for (; t + 4 <= n; t += 4) {
            int s0 = __shfl_sync(0xFFFFFFFFu, si, t);
            int s1 = __shfl_sync(0xFFFFFFFFu, si, t + 1);
            int s2 = __shfl_sync(0xFFFFFFFFu, si, t + 2);
            int s3 = __shfl_sync(0xFFFFFFFFu, si, t + 3);
            acc_row(acc, Hs, s0, lane);
            acc_row(acc, Hs, s1, lane);
            acc_row(acc, Hs, s2, lane);
            acc_row(acc, Hs, s3, lane);
        }
        for (; t < n; t++) {
            int s0 = __shfl_sync(0xFFFFFFFFu, si, t);
            acc_row(acc, Hs, s0, lane);
        }
    }

    float dd = __ldg(&g_dis[node]);
    float4 b4 = *(const float4*)(bias + lane * 4);
    acc.x = fmaxf(acc.x * dd + b4.x, 0.f);
    acc.y = fmaxf(acc.y * dd + b4.y, 0.f);
    acc.z = fmaxf(acc.z * dd + b4.z, 0.f);
    acc.w = fmaxf(acc.w * dd + b4.w, 0.f);

    if (MODE == 0) {
        uint2 o;
        *(__half2*)&o.x = __floats2half2_rn(acc.x, acc.y);
        *(__half2*)&o.y = __floats2half2_rn(acc.z, acc.w);
        *(uint2*)(OUT + (size_t)node * CH + lane * 4) = o;
    } else {
        float4 w4 = *(const float4*)(Wfc + lane * 4);
        float s = acc.x * w4.x + acc.y * w4.y + acc.z * w4.z + acc.w * w4.w;
        #pragma unroll
        for (int o = 16; o; o >>= 1) s += __shfl_xor_sync(0xFFFFFFFFu, s, o);
        if (lane == 0) atomicAdd(&g_gsum[__ldg(batch + node)], s);
    }
}

// ---------------- pooling helpers ----------------
__global__ void graph_cnt_kernel(const int* __restrict__ batch) {
    int i = blockIdx.x * blockDim.x + threadIdx.x;
    if (i < N_NODES_C) atomicAdd(&g_gcnt[batch[i]], 1.0f);
}

__global__ void final_out_kernel(float* __restrict__ out, const float* __restrict__ bfc) {
    int g = threadIdx.x;
    if (g < N_GRAPHS_C)
        out[g] = g_gsum[g] / fmaxf(g_gcnt[g], 1.0f) + bfc[0];
}

// ---------------- launch ----------------
extern "C" void kernel_launch(void* const* d_in, const int* in_sizes, int n_in,
                              void* d_out, int out_size)
{
    const float* x    = (const float*)d_in[0];
    const int*   edge = (const int*)  d_in[1];
    const int*   batch= (const int*)  d_in[2];
    const float* W1   = (const float*)d_in[3];
    const float* b1   = (const float*)d_in[4];
    const float* W2   = (const float*)d_in[5];
    const float* b2   = (const float*)d_in[6];
    const float* Wfc  = (const float*)d_in[7];
    const float* bfc  = (const float*)d_in[8];
    float* out = (float*)d_out;

    const int* srcp = edge;
    const int* dstp = edge + N_EDGES_C;

    __half *bufA = nullptr, *bufB = nullptr;
    float *disp = nullptr;
    cudaGetSymbolAddress((void**)&bufA, g_bufA);
    cudaGetSymbolAddress((void**)&bufB, g_bufB);
    cudaGetSymbolAddress((void**)&disp, g_dis);

    const int ngrid  = NBLK;
    const int e2grid = (N_EDGES_C / 2 + 255) / 256;
    const int agrid  = (N_NODES_C + 7) / 8;
    const int ggrid  = (N_NODES_C + 127) / 128;

    // ---- zero counters (plain kernel launch; capture-safe) ----
    zero_counters_kernel<<<ngrid, 256>>>();

    // ---- degree + CSR (by dst) ----
    cnt_count_kernel<<<e2grid, 256>>>(dstp);
    partial_sum_kernel<<<ngrid, 256>>>();
    scan_block_kernel<<<1, 512>>>();
    rowptr_fill_kernel<<<ngrid, 256>>>();
    csr_fill_kernel<<<e2grid, 256>>>(srcp, dstp);
    graph_cnt_kernel<<<ngrid, 256>>>(batch);

    // ---- layer 1:  Hs = half((X@W1)*dis)  -> gather -> relu(+b1) -> fp16 ----
    gemm_tf32_kernel<float><<<ggrid, 256>>>(x, W1, bufA, disp, N_NODES_C);
    agg_kernel<0><<<agrid, 256>>>(bufA, b1, bufB, nullptr, nullptr);

    // ---- layer 2:  Hs = half((h1@W2)*dis) -> gather -> relu(+b2) -> pooled FC dot ----
    gemm_tf32_kernel<__half><<<ggrid, 256>>>(bufB, W2, bufA, disp, N_NODES_C);
    agg_kernel<1><<<agrid, 256>>>(bufA, b2, nullptr, Wfc, batch);

    // ---- final ----
    final_out_kernel<<<1, 256>>>(out, bfc);

    (void)in_sizes; (void)n_in; (void)out_size;
}

// round 9
// speedup vs baseline: 2.4088x; 1.0126x over previous
#include <cuda_runtime.h>
#include <cuda_fp16.h>
#include <cstdint>

#define N_NODES_C  100000
#define N_EDGES_C  1600000
#define CH         128
#define N_GRAPHS_C 256
#define NBLK       ((N_NODES_C + 255) / 256)   // 391

// ---------------- scratch (static device globals; zero-initialized at load) ----------------
__device__ __half g_bufA[(size_t)N_NODES_C * CH];  // 25.6 MB (Hs, fp16)
__device__ __half g_bufB[(size_t)N_NODES_C * CH];  // 25.6 MB (h1, fp16)
__device__ float g_dis[N_NODES_C];                 // deg^-0.5
__device__ int   g_cnt[N_NODES_C];                 // in-degree histogram (reset by scan kernel)
__device__ int   g_rowptr[N_NODES_C + 1];
__device__ int   g_cursor[N_NODES_C];
__device__ int   g_csr_src[N_EDGES_C];
__device__ unsigned long long g_scan_state[512];   // (flag<<32)|sum ; flag 1=agg, 2=prefix (reset by csr_fill)
__device__ float g_gsum[N_GRAPHS_C];               // reset by final_out
__device__ float g_gcnt[N_GRAPHS_C];               // reset by final_out

// ---------------- degree count + graph count (fused; one pass over edges + nodes) ----------------
__global__ void cnt_count_kernel(const int* __restrict__ dst, const int* __restrict__ batch) {
    int i = blockIdx.x * blockDim.x + threadIdx.x;
    if (i * 2 + 1 < N_EDGES_C) {
        int2 d = *(const int2*)(dst + i * 2);
        atomicAdd(&g_cnt[d.x], 1);
        atomicAdd(&g_cnt[d.y], 1);
    } else if (i * 2 < N_EDGES_C) {
        atomicAdd(&g_cnt[dst[i * 2]], 1);
    }
    if (i < N_NODES_C) atomicAdd(&g_gcnt[batch[i]], 1.0f);
}

// ---------------- single-pass decoupled-lookback scan + rowptr/cursor/dis + cnt reset ----------------
__global__ __launch_bounds__(256) void scan_lookback_kernel() {
    __shared__ int s[256];
    __shared__ int sP;
    const int b = blockIdx.x;
    const int t = threadIdx.x;
    const int i = b * 256 + t;

    int c = (i < N_NODES_C) ? g_cnt[i] : 0;
    s[t] = c;
    __syncthreads();
    // Hillis-Steele inclusive scan over 256
    for (int o = 1; o < 256; o <<= 1) {
        int u = (t >= o) ? s[t - o] : 0;
        __syncthreads();
        s[t] += u;
        __syncthreads();
    }
    const int total = s[255];

    if (b == 0) {
        if (t == 0) {
            atomicExch(&g_scan_state[0], (2ull << 32) | (unsigned)total);
            sP = 0;
        }
    } else {
        if (t == 0)   // publish aggregate early so successors can proceed
            atomicExch(&g_scan_state[b], (1ull << 32) | (unsigned)total);
        if (t < 32) { // warp-parallel lookback
            int lane = t;
            int P = 0;
            int j = b - 1;
            while (true) {
                int idx = j - lane;
                int flag = 0, val = 0;
                if (idx >= 0) {
                    unsigned long long v;
                    do { v = atomicAdd(&g_scan_state[idx], 0ull); flag = (int)(v >> 32); }
                    while (flag == 0);
                    val = (int)(v & 0xffffffffu);
                }
                unsigned m = __ballot_sync(0xFFFFFFFFu, (idx >= 0) && (flag == 2));
                if (m) {
                    int firstP = __ffs(m) - 1;            // nearest predecessor with full prefix
                    int contrib = (lane <= firstP) ? val : 0;
                    P += __reduce_add_sync(0xFFFFFFFFu, contrib);
                    break;
                } else {
                    P += __reduce_add_sync(0xFFFFFFFFu, (idx >= 0) ? val : 0);
                    j -= 32;
                }
            }
            if (lane == 0) {
                atomicExch(&g_scan_state[b], (2ull << 32) | (unsigned)(P + total));
                sP = P;
            }
        }
    }
    __syncthreads();

    if (i < N_NODES_C) {
        int pos = sP + s[t] - c;                  // global exclusive prefix
        g_rowptr[i] = pos;
        g_cursor[i] = pos;
        g_dis[i]    = rsqrtf(1.0f + (float)c);
        g_cnt[i]    = 0;                          // reset for next call
    }
    if (b == 0 && t == 0) g_rowptr[N_NODES_C] = N_EDGES_C;
}

// ---------------- CSR fill (+ scan-state reset for next call) ----------------
__global__ void csr_fill_kernel(const int* __restrict__ src, const int* __restrict__ dst) {
    int i = blockIdx.x * blockDim.x + threadIdx.x;
    if (i < 512) g_scan_state[i] = 0ull;          // scan already complete (stream order)
    if (i * 2 + 1 < N_EDGES_C) {
        int2 s = *(const int2*)(src + i * 2);
        int2 d = *(const int2*)(dst + i * 2);
        g_csr_src[atomicAdd(&g_cursor[d.x], 1)] = s.x;
        g_csr_src[atomicAdd(&g_cursor[d.y], 1)] = s.y;
    } else if (i * 2 < N_EDGES_C) {
        g_csr_src[atomicAdd(&g_cursor[dst[i * 2]], 1)] = src[i * 2];
    }
}

// ---------------- tf32 tensor-core GEMM: Y[r,:] = half((X[r,:] @ W) * scale[r]) ----------------
__device__ __forceinline__ uint32_t f2tf32(float v) {
    uint32_t t;
    asm("cvt.rna.tf32.f32 %0, %1;" : "=r"(t) : "f"(v));
    return t;
}
__device__ __forceinline__ float ld_as_float(const float* p)  { return __ldg(p); }
__device__ __forceinline__ float ld_as_float(const __half* p) { return __half2float(__ldg(p)); }

template <typename T>
__global__ __launch_bounds__(256) void gemm_tf32_kernel(
    const T* __restrict__ X, const float* __restrict__ W,
    __half* __restrict__ Y, const float* __restrict__ scale, int M)
{
    __shared__ uint32_t sB[8192];            // 32 KB: one N-half of W, fragment-packed

    const int tid  = threadIdx.x;
    const int warp = tid >> 5;
    const int lane = tid & 31;
    const int gid  = lane >> 2;
    const int tig  = lane & 3;
    const int rowBase = blockIdx.x * 128;

    const int r0 = rowBase + warp * 16 + gid;
    const int r1 = r0 + 8;
    const bool v0 = (r0 < M);
    const bool v1 = (r1 < M);
    const T* X0 = X + (size_t)r0 * CH;
    const T* X1 = X + (size_t)r1 * CH;

    uint32_t a[16][4];
    #pragma unroll
    for (int kk = 0; kk < 16; kk++) {
        int c0 = kk * 8 + tig;
        a[kk][0] = v0 ? f2tf32(ld_as_float(X0 + c0))     : 0u;
        a[kk][1] = v1 ? f2tf32(ld_as_float(X1 + c0))     : 0u;
        a[kk][2] = v0 ? f2tf32(ld_as_float(X0 + c0 + 4)) : 0u;
        a[kk][3] = v1 ? f2tf32(ld_as_float(X1 + c0 + 4)) : 0u;
    }

    float acc[16][4];
    #pragma unroll
    for (int nt = 0; nt < 16; nt++)
        #pragma unroll
        for (int j = 0; j < 4; j++) acc[nt][j] = 0.f;

    #pragma unroll
    for (int h = 0; h < 2; h++) {
        #pragma unroll
        for (int v = 0; v < 32; v++) {
            int idx   = tid + v * 256;
            int half_ = idx & 1;
            int lane_ = (idx >> 1) & 31;
            int ntp   = (idx >> 6) & 7;
            int kk    = idx >> 9;
            int k = kk * 8 + (lane_ & 3) + half_ * 4;
            int n = h * 64 + ntp * 8 + (lane_ >> 2);
            sB[idx] = f2tf32(__ldg(W + (size_t)k * CH + n));
        }
        __syncthreads();

        #pragma unroll
        for (int kk = 0; kk < 16; kk++) {
            #pragma unroll
            for (int ntp = 0; ntp < 8; ntp++) {
                uint2 b = *(const uint2*)(sB + (kk * 8 + ntp) * 64 + lane * 2);
                float* c = acc[h * 8 + ntp];
                asm volatile(
                    "mma.sync.aligned.m16n8k8.row.col.f32.tf32.tf32.f32 "
                    "{%0,%1,%2,%3}, {%4,%5,%6,%7}, {%8,%9}, {%0,%1,%2,%3};"
                    : "+f"(c[0]), "+f"(c[1]), "+f"(c[2]), "+f"(c[3])
                    : "r"(a[kk][0]), "r"(a[kk][1]), "r"(a[kk][2]), "r"(a[kk][3]),
                      "r"(b.x), "r"(b.y));
            }
        }
        __syncthreads();
    }

    float s0 = v0 ? scale[r0] : 0.f;
    float s1 = v1 ? scale[r1] : 0.f;
    #pragma unroll
    for (int nt = 0; nt < 16; nt++) {
        int col = nt * 8 + tig * 2;
        if (v0)
            *(__half2*)(Y + (size_t)r0 * CH + col) =
                __floats2half2_rn(acc[nt][0] * s0, acc[nt][1] * s0);
        if (v1)
            *(__half2*)(Y + (size_t)r1 * CH + col) =
                __floats2half2_rn(acc[nt][2] * s1, acc[nt][3] * s1);
    }
}

// ---------------- gather aggregation (fp16 Hs rows pre-scaled by dis[row]) ----------------
__device__ __forceinline__ void acc_row(float4& acc, const __half* Hs, int srow, int lane) {
    uint2 raw = *(const uint2*)(Hs + (size_t)srow * CH + lane * 4);
    float2 f0 = __half22float2(*(__half2*)&raw.x);
    float2 f1 = __half22float2(*(__half2*)&raw.y);
    acc.x += f0.x; acc.y += f0.y; acc.z += f1.x; acc.w += f1.y;
}

template <int MODE>
__global__ __launch_bounds__(256) void agg_kernel(
    const __half* __restrict__ Hs, const float* __restrict__ bias,
    __half* __restrict__ OUT,
    const float* __restrict__ Wfc, const int* __restrict__ batch)
{
    int node = (blockIdx.x * blockDim.x + threadIdx.x) >> 5;
    int lane = threadIdx.x & 31;
    if (node >= N_NODES_C) return;

    float4 acc = make_float4(0.f, 0.f, 0.f, 0.f);
    acc_row(acc, Hs, node, lane);            // self term

    int beg = __ldg(&g_rowptr[node]);
    int end = __ldg(&g_rowptr[node + 1]);

    for (int j = beg; j < end; j += 32) {
        int n = min(32, end - j);
        int si = (lane < n) ? __ldg(&g_csr_src[j + lane]) : 0;
        int t = 0;
        for (; t + 8 <= n; t += 8) {         // 8 independent row loads in flight
            int ss[8];
            #pragma unroll
            for (int k = 0; k < 8; k++) ss[k] = __shfl_sync(0xFFFFFFFFu, si, t + k);
            #pragma unroll
            for (int k = 0; k < 8; k++) acc_row(acc, Hs, ss[k], lane);
        }
        for (; t + 2 <= n; t += 2) {
            int s0 = __shfl_sync(0xFFFFFFFFu, si, t);
            int s1 = __shfl_sync(0xFFFFFFFFu, si, t + 1);
            acc_row(acc, Hs, s0, lane);
            acc_row(acc, Hs, s1, lane);
        }
        if (t < n) {
            int s0 = __shfl_sync(0xFFFFFFFFu, si, t);
            acc_row(acc, Hs, s0, lane);
        }
    }

    float dd = __ldg(&g_dis[node]);
    float4 b4 = *(const float4*)(bias + lane * 4);
    acc.x = fmaxf(acc.x * dd + b4.x, 0.f);
    acc.y = fmaxf(acc.y * dd + b4.y, 0.f);
    acc.z = fmaxf(acc.z * dd + b4.z, 0.f);
    acc.w = fmaxf(acc.w * dd + b4.w, 0.f);

    if (MODE == 0) {
        uint2 o;
        *(__half2*)&o.x = __floats2half2_rn(acc.x, acc.y);
        *(__half2*)&o.y = __floats2half2_rn(acc.z, acc.w);
        *(uint2*)(OUT + (size_t)node * CH + lane * 4) = o;
    } else {
        float4 w4 = *(const float4*)(Wfc + lane * 4);
        float s = acc.x * w4.x + acc.y * w4.y + acc.z * w4.z + acc.w * w4.w;
        #pragma unroll
        for (int o = 16; o; o >>= 1) s += __shfl_xor_sync(0xFFFFFFFFu, s, o);
        if (lane == 0) atomicAdd(&g_gsum[__ldg(batch + node)], s);
    }
}

// ---------------- final output (+ pool-state reset for next call) ----------------
__global__ void final_out_kernel(float* __restrict__ out, const float* __restrict__ bfc) {
    int g = threadIdx.x;
    if (g < N_GRAPHS_C) {
        out[g] = g_gsum[g] / fmaxf(g_gcnt[g], 1.0f) + bfc[0];
        g_gsum[g] = 0.f;
        g_gcnt[g] = 0.f;
    }
}

// ---------------- launch (8 kernels, plain launches only) ----------------
extern "C" void kernel_launch(void* const* d_in, const int* in_sizes, int n_in,
                              void* d_out, int out_size)
{
    const float* x    = (const float*)d_in[0];
    const int*   edge = (const int*)  d_in[1];
    const int*   batch= (const int*)  d_in[2];
    const float* W1   = (const float*)d_in[3];
    const float* b1   = (const float*)d_in[4];
    const float* W2   = (const float*)d_in[5];
    const float* b2   = (const float*)d_in[6];
    const float* Wfc  = (const float*)d_in[7];
    const float* bfc  = (const float*)d_in[8];
    float* out = (float*)d_out;

    const int* srcp = edge;
    const int* dstp = edge + N_EDGES_C;

    __half *bufA = nullptr, *bufB = nullptr;
    float *disp = nullptr;
    cudaGetSymbolAddress((void**)&bufA, g_bufA);
    cudaGetSymbolAddress((void**)&bufB, g_bufB);
    cudaGetSymbolAddress((void**)&disp, g_dis);

    const int e2grid = (N_EDGES_C / 2 + 255) / 256;
    const int agrid  = (N_NODES_C + 7) / 8;
    const int ggrid  = (N_NODES_C + 127) / 128;

    // ---- CSR build: 3 launches ----
    cnt_count_kernel<<<e2grid, 256>>>(dstp, batch);
    scan_lookback_kernel<<<NBLK, 256>>>();
    csr_fill_kernel<<<e2grid, 256>>>(srcp, dstp);

    // ---- layer 1:  Hs = half((X@W1)*dis)  -> gather -> relu(+b1) -> fp16 ----
    gemm_tf32_kernel<float><<<ggrid, 256>>>(x, W1, bufA, disp, N_NODES_C);
    agg_kernel<0><<<agrid, 256>>>(bufA, b1, bufB, nullptr, nullptr);

    // ---- layer 2:  Hs = half((h1@W2)*dis) -> gather -> relu(+b2) -> pooled FC dot ----
    gemm_tf32_kernel<__half><<<ggrid, 256>>>(bufB, W2, bufA, disp, N_NODES_C);
    agg_kernel<1><<<agrid, 256>>>(bufA, b2, nullptr, Wfc, batch);

    // ---- final (+ reset pooling state) ----
    final_out_kernel<<<1, 256>>>(out, bfc);

    (void)in_sizes; (void)n_in; (void)out_size;
}

// round 11
// speedup vs baseline: 2.7163x; 1.1277x over previous
#include <cuda_runtime.h>
#include <cuda_fp16.h>
#include <cstdint>

#define N_NODES_C  100000
#define N_EDGES_C  1600000
#define CH         128
#define N_GRAPHS_C 256
#define NBLK       ((N_NODES_C + 255) / 256)   // 391
#define SXP        136                          // padded smem X row stride (halves)

// ---------------- scratch (static device globals; zero-initialized at load) ----------------
__device__ __half g_bufA[(size_t)N_NODES_C * CH];  // 25.6 MB (Hs, fp16)
__device__ __half g_bufB[(size_t)N_NODES_C * CH];  // 25.6 MB (h1, fp16)
__device__ float g_dis[N_NODES_C];                 // deg^-0.5
__device__ int   g_cnt[N_NODES_C];                 // in-degree histogram (reset by scan kernel)
__device__ int   g_rowptr[N_NODES_C + 1];
__device__ int   g_cursor[N_NODES_C];
__device__ int   g_csr_src[N_EDGES_C];
__device__ unsigned long long g_scan_state[512];   // (flag<<32)|sum (reset by csr_fill)
__device__ float g_gsum[N_GRAPHS_C];               // reset by final_out
__device__ float g_gcnt[N_GRAPHS_C];               // reset by final_out

// bit-cast __half2 -> uint32_t (compiles to a register no-op)
__device__ __forceinline__ uint32_t h2u(__half2 h) {
    union { __half2 h; uint32_t u; } c;
    c.h = h;
    return c.u;
}

// ---------------- degree count + graph count (fused) ----------------
__global__ void cnt_count_kernel(const int* __restrict__ dst, const int* __restrict__ batch) {
    int i = blockIdx.x * blockDim.x + threadIdx.x;
    if (i * 2 + 1 < N_EDGES_C) {
        int2 d = *(const int2*)(dst + i * 2);
        atomicAdd(&g_cnt[d.x], 1);
        atomicAdd(&g_cnt[d.y], 1);
    } else if (i * 2 < N_EDGES_C) {
        atomicAdd(&g_cnt[dst[i * 2]], 1);
    }
    if (i < N_NODES_C) atomicAdd(&g_gcnt[batch[i]], 1.0f);
}

// ---------------- single-pass decoupled-lookback scan + rowptr/cursor/dis + cnt reset ----------------
__global__ __launch_bounds__(256) void scan_lookback_kernel() {
    __shared__ int s[256];
    __shared__ int sP;
    const int b = blockIdx.x;
    const int t = threadIdx.x;
    const int i = b * 256 + t;

    int c = (i < N_NODES_C) ? g_cnt[i] : 0;
    s[t] = c;
    __syncthreads();
    for (int o = 1; o < 256; o <<= 1) {
        int u = (t >= o) ? s[t - o] : 0;
        __syncthreads();
        s[t] += u;
        __syncthreads();
    }
    const int total = s[255];

    if (b == 0) {
        if (t == 0) {
            atomicExch(&g_scan_state[0], (2ull << 32) | (unsigned)total);
            sP = 0;
        }
    } else {
        if (t == 0)
            atomicExch(&g_scan_state[b], (1ull << 32) | (unsigned)total);
        if (t < 32) {
            int lane = t;
            int P = 0;
            int j = b - 1;
            while (true) {
                int idx = j - lane;
                int flag = 0, val = 0;
                if (idx >= 0) {
                    unsigned long long v;
                    do { v = atomicAdd(&g_scan_state[idx], 0ull); flag = (int)(v >> 32); }
                    while (flag == 0);
                    val = (int)(v & 0xffffffffu);
                }
                unsigned m = __ballot_sync(0xFFFFFFFFu, (idx >= 0) && (flag == 2));
                if (m) {
                    int firstP = __ffs(m) - 1;
                    int contrib = (lane <= firstP) ? val : 0;
                    P += __reduce_add_sync(0xFFFFFFFFu, contrib);
                    break;
                } else {
                    P += __reduce_add_sync(0xFFFFFFFFu, (idx >= 0) ? val : 0);
                    j -= 32;
                }
            }
            if (lane == 0) {
                atomicExch(&g_scan_state[b], (2ull << 32) | (unsigned)(P + total));
                sP = P;
            }
        }
    }
    __syncthreads();

    if (i < N_NODES_C) {
        int pos = sP + s[t] - c;
        g_rowptr[i] = pos;
        g_cursor[i] = pos;
        g_dis[i]    = rsqrtf(1.0f + (float)c);
        g_cnt[i]    = 0;
    }
    if (b == 0 && t == 0) g_rowptr[N_NODES_C] = N_EDGES_C;
}

// ---------------- CSR fill (+ scan-state reset) ----------------
__global__ void csr_fill_kernel(const int* __restrict__ src, const int* __restrict__ dst) {
    int i = blockIdx.x * blockDim.x + threadIdx.x;
    if (i < 512) g_scan_state[i] = 0ull;
    if (i * 2 + 1 < N_EDGES_C) {
        int2 s = *(const int2*)(src + i * 2);
        int2 d = *(const int2*)(dst + i * 2);
        g_csr_src[atomicAdd(&g_cursor[d.x], 1)] = s.x;
        g_csr_src[atomicAdd(&g_cursor[d.y], 1)] = s.y;
    } else if (i * 2 < N_EDGES_C) {
        g_csr_src[atomicAdd(&g_cursor[dst[i * 2]], 1)] = src[i * 2];
    }
}

// ---------------- fp16 tensor-core GEMM: Y[r,:] = half((X[r,:] @ W) * scale[r]) ----------------
// 256 threads (8 warps), 128 rows/block, K=128 via m16n8k16, N in four 32-col quarters.
// X staged in smem fp16 (padded, conflict-free); W quarter fragment-packed in 8KB smem.
template <typename T>
__global__ __launch_bounds__(256) void gemm_f16_kernel(
    const T* __restrict__ X, const float* __restrict__ W,
    __half* __restrict__ Y, const float* __restrict__ scale, int M)
{
    __shared__ __half    sX[128 * SXP];      // 34816 B
    __shared__ uint32_t  sB[2048];           // 8192 B (one N-quarter of W)

    const int tid  = threadIdx.x;
    const int warp = tid >> 5;
    const int lane = tid & 31;
    const int gid  = lane >> 2;
    const int tig  = lane & 3;
    const int rowBase = blockIdx.x * 128;

    // ---- stage X tile into smem as fp16 ----
    if (sizeof(T) == 4) {                    // fp32 input (layer 1)
        const float* Xf = (const float*)X;
        #pragma unroll
        for (int v = 0; v < 16; v++) {
            int fi = tid + v * 256;          // 4096 float4
            int r  = fi >> 5;
            int c4 = (fi & 31) * 4;
            float4 val = make_float4(0.f, 0.f, 0.f, 0.f);
            int gr = rowBase + r;
            if (gr < M) val = *(const float4*)(Xf + (size_t)gr * CH + c4);
            uint32_t* p = (uint32_t*)(sX + r * SXP + c4);
            p[0] = h2u(__floats2half2_rn(val.x, val.y));
            p[1] = h2u(__floats2half2_rn(val.z, val.w));
        }
    } else {                                 // fp16 input (layer 2)
        const __half* Xh = (const __half*)X;
        #pragma unroll
        for (int v = 0; v < 8; v++) {
            int fi = tid + v * 256;          // 2048 uint4 (8 halves each)
            int r  = fi >> 4;
            int c8 = (fi & 15) * 8;
            uint4 val = make_uint4(0u, 0u, 0u, 0u);
            int gr = rowBase + r;
            if (gr < M) val = *(const uint4*)(Xh + (size_t)gr * CH + c8);
            uint32_t* p = (uint32_t*)(sX + r * SXP + c8);
            p[0] = val.x; p[1] = val.y; p[2] = val.z; p[3] = val.w;
        }
    }

    float acc[16][4];
    #pragma unroll
    for (int nt = 0; nt < 16; nt++)
        #pragma unroll
        for (int j = 0; j < 4; j++) acc[nt][j] = 0.f;

    const int arow = warp * 16 + gid;        // this warp's A rows: arow, arow+8

    // ---- four N-quarters ----
    #pragma unroll
    for (int q = 0; q < 4; q++) {
        // pack W[:, q*32 .. q*32+31] into fragments:
        // idx = kk*256 + ntp*64 + lane_*2 + r
        // value = half2( W[k][n], W[k+1][n] ), k = kk*16 + r*8 + (lane_&3)*2, n = q*32 + ntp*8 + (lane_>>2)
        #pragma unroll
        for (int v = 0; v < 8; v++) {
            int idx   = tid + v * 256;
            int r     = idx & 1;
            int lane_ = (idx >> 1) & 31;
            int ntp   = (idx >> 6) & 3;
            int kk    = idx >> 8;
            int k = kk * 16 + r * 8 + (lane_ & 3) * 2;
            int n = q * 32 + ntp * 8 + (lane_ >> 2);
            float w0 = __ldg(W + (size_t)k * CH + n);
            float w1 = __ldg(W + (size_t)(k + 1) * CH + n);
            sB[idx] = h2u(__floats2half2_rn(w0, w1));
        }
        __syncthreads();

        #pragma unroll
        for (int kk = 0; kk < 8; kk++) {
            // A fragments from smem (conflict-free: bank = lane identity)
            uint32_t a0 = *(const uint32_t*)(sX + arow * SXP       + kk * 16 + tig * 2);
            uint32_t a1 = *(const uint32_t*)(sX + (arow + 8) * SXP + kk * 16 + tig * 2);
            uint32_t a2 = *(const uint32_t*)(sX + arow * SXP       + kk * 16 + tig * 2 + 8);
            uint32_t a3 = *(const uint32_t*)(sX + (arow + 8) * SXP + kk * 16 + tig * 2 + 8);
            #pragma unroll
            for (int ntp = 0; ntp < 4; ntp++) {
                uint2 b = *(const uint2*)(sB + kk * 256 + ntp * 64 + lane * 2);
                float* c = acc[q * 4 + ntp];
                asm volatile(
                    "mma.sync.aligned.m16n8k16.row.col.f32.f16.f16.f32 "
                    "{%0,%1,%2,%3}, {%4,%5,%6,%7}, {%8,%9}, {%0,%1,%2,%3};"
                    : "+f"(c[0]), "+f"(c[1]), "+f"(c[2]), "+f"(c[3])
                    : "r"(a0), "r"(a1), "r"(a2), "r"(a3), "r"(b.x), "r"(b.y));
            }
        }
        __syncthreads();
    }

    // ---- epilogue: scale rows by dis[row], convert fp16, store ----
    const int r0 = rowBase + warp * 16 + gid;
    const int r1 = r0 + 8;
    const bool v0 = (r0 < M);
    const bool v1 = (r1 < M);
    float s0 = v0 ? scale[r0] : 0.f;
    float s1 = v1 ? scale[r1] : 0.f;
    #pragma unroll
    for (int nt = 0; nt < 16; nt++) {
        int col = nt * 8 + tig * 2;
        if (v0)
            *(__half2*)(Y + (size_t)r0 * CH + col) =
                __floats2half2_rn(acc[nt][0] * s0, acc[nt][1] * s0);
        if (v1)
            *(__half2*)(Y + (size_t)r1 * CH + col) =
                __floats2half2_rn(acc[nt][2] * s1, acc[nt][3] * s1);
    }
}

// ---------------- gather aggregation (fp16 Hs rows pre-scaled by dis[row]) ----------------
__device__ __forceinline__ void acc_row(float4& acc, const __half* Hs, int srow, int lane) {
    uint2 raw = *(const uint2*)(Hs + (size_t)srow * CH + lane * 4);
    float2 f0 = __half22float2(*(__half2*)&raw.x);
    float2 f1 = __half22float2(*(__half2*)&raw.y);
    acc.x += f0.x; acc.y += f0.y; acc.z += f1.x; acc.w += f1.y;
}

template <int MODE>
__global__ __launch_bounds__(256) void agg_kernel(
    const __half* __restrict__ Hs, const float* __restrict__ bias,
    __half* __restrict__ OUT,
    const float* __restrict__ Wfc, const int* __restrict__ batch)
{
    int node = (blockIdx.x * blockDim.x + threadIdx.x) >> 5;
    int lane = threadIdx.x & 31;
    if (node >= N_NODES_C) return;

    float4 acc = make_float4(0.f, 0.f, 0.f, 0.f);
    acc_row(acc, Hs, node, lane);            // self term

    int beg = __ldg(&g_rowptr[node]);
    int end = __ldg(&g_rowptr[node + 1]);

    for (int j = beg; j < end; j += 32) {
        int n = min(32, end - j);
        int si = (lane < n) ? __ldg(&g_csr_src[j + lane]) : 0;
        int t = 0;
        for (; t + 8 <= n; t += 8) {
            int ss[8];
            #pragma unroll
            for (int k = 0; k < 8; k++) ss[k] = __shfl_sync(0xFFFFFFFFu, si, t + k);
            #pragma unroll
            for (int k = 0; k < 8; k++) acc_row(acc, Hs, ss[k], lane);
        }
        for (; t + 2 <= n; t += 2) {
            int s0 = __shfl_sync(0xFFFFFFFFu, si, t);
            int s1 = __shfl_sync(0xFFFFFFFFu, si, t + 1);
            acc_row(acc, Hs, s0, lane);
            acc_row(acc, Hs, s1, lane);
        }
        if (t < n) {
            int s0 = __shfl_sync(0xFFFFFFFFu, si, t);
            acc_row(acc, Hs, s0, lane);
        }
    }

    float dd = __ldg(&g_dis[node]);
    float4 b4 = *(const float4*)(bias + lane * 4);
    acc.x = fmaxf(acc.x * dd + b4.x, 0.f);
    acc.y = fmaxf(acc.y * dd + b4.y, 0.f);
    acc.z = fmaxf(acc.z * dd + b4.z, 0.f);
    acc.w = fmaxf(acc.w * dd + b4.w, 0.f);

    if (MODE == 0) {
        uint2 o;
        o.x = h2u(__floats2half2_rn(acc.x, acc.y));
        o.y = h2u(__floats2half2_rn(acc.z, acc.w));
        *(uint2*)(OUT + (size_t)node * CH + lane * 4) = o;
    } else {
        float4 w4 = *(const float4*)(Wfc + lane * 4);
        float s = acc.x * w4.x + acc.y * w4.y + acc.z * w4.z + acc.w * w4.w;
        #pragma unroll
        for (int o = 16; o; o >>= 1) s += __shfl_xor_sync(0xFFFFFFFFu, s, o);
        if (lane == 0) atomicAdd(&g_gsum[__ldg(batch + node)], s);
    }
}

// ---------------- final output (+ pool-state reset) ----------------
__global__ void final_out_kernel(float* __restrict__ out, const float* __restrict__ bfc) {
    int g = threadIdx.x;
    if (g < N_GRAPHS_C) {
        out[g] = g_gsum[g] / fmaxf(g_gcnt[g], 1.0f) + bfc[0];
        g_gsum[g] = 0.f;
        g_gcnt[g] = 0.f;
    }
}

// ---------------- launch (8 kernels, plain launches only) ----------------
extern "C" void kernel_launch(void* const* d_in, const int* in_sizes, int n_in,
                              void* d_out, int out_size)
{
    const float* x    = (const float*)d_in[0];
    const int*   edge = (const int*)  d_in[1];
    const int*   batch= (const int*)  d_in[2];
    const float* W1   = (const float*)d_in[3];
    const float* b1   = (const float*)d_in[4];
    const float* W2   = (const float*)d_in[5];
    const float* b2   = (const float*)d_in[6];
    const float* Wfc  = (const float*)d_in[7];
    const float* bfc  = (const float*)d_in[8];
    float* out = (float*)d_out;

    const int* srcp = edge;
    const int* dstp = edge + N_EDGES_C;

    __half *bufA = nullptr, *bufB = nullptr;
    float *disp = nullptr;
    cudaGetSymbolAddress((void**)&bufA, g_bufA);
    cudaGetSymbolAddress((void**)&bufB, g_bufB);
    cudaGetSymbolAddress((void**)&disp, g_dis);

    const int e2grid = (N_EDGES_C / 2 + 255) / 256;
    const int agrid  = (N_NODES_C + 7) / 8;
    const int ggrid  = (N_NODES_C + 127) / 128;

    // ---- CSR build: 3 launches ----
    cnt_count_kernel<<<e2grid, 256>>>(dstp, batch);
    scan_lookback_kernel<<<NBLK, 256>>>();
    csr_fill_kernel<<<e2grid, 256>>>(srcp, dstp);

    // ---- layer 1:  Hs = half((X@W1)*dis)  -> gather -> relu(+b1) -> fp16 ----
    gemm_f16_kernel<float><<<ggrid, 256>>>(x, W1, bufA, disp, N_NODES_C);
    agg_kernel<0><<<agrid, 256>>>(bufA, b1, bufB, nullptr, nullptr);

    // ---- layer 2:  Hs = half((h1@W2)*dis) -> gather -> relu(+b2) -> pooled FC dot ----
    gemm_f16_kernel<__half><<<ggrid, 256>>>(bufB, W2, bufA, disp, N_NODES_C);
    agg_kernel<1><<<agrid, 256>>>(bufA, b2, nullptr, Wfc, batch);

    // ---- final (+ reset pooling state) ----
    final_out_kernel<<<1, 256>>>(out, bfc);

    (void)in_sizes; (void)n_in; (void)out_size;
}

// round 12
// speedup vs baseline: 2.8582x; 1.0522x over previous
#include <cuda_runtime.h>
#include <cuda_fp16.h>
#include <cstdint>

#define N_NODES_C  100000
#define N_EDGES_C  1600000
#define CH         128
#define N_GRAPHS_C 256
#define NBLK       ((N_NODES_C + 255) / 256)   // 391
#define SXP        136                          // padded smem X row stride (halves)

// ---------------- scratch (static device globals; zero-initialized at load) ----------------
__device__ __half g_bufA[(size_t)N_NODES_C * CH];  // 25.6 MB (Hs, fp16)
__device__ __half g_bufB[(size_t)N_NODES_C * CH];  // 25.6 MB (h1, fp16)
__device__ float g_dis[N_NODES_C];                 // deg^-0.5
__device__ int   g_cnt[N_NODES_C];                 // in-degree histogram (reset by scan kernel)
__device__ int   g_rowptr[N_NODES_C + 1];
__device__ int   g_cursor[N_NODES_C];
__device__ int   g_csr_src[N_EDGES_C];
__device__ unsigned long long g_scan_state[512];   // (flag<<32)|sum (reset by csr_fill)
__device__ float g_gsum[N_GRAPHS_C];               // reset by final_out
__device__ float g_gcnt[N_GRAPHS_C];               // reset by final_out
__device__ uint32_t g_W1p[8192];                   // fragment-packed fp16 W1 (32 KB)
__device__ uint32_t g_W2p[8192];                   // fragment-packed fp16 W2 (32 KB)

// bit-cast __half2 -> uint32_t (register no-op)
__device__ __forceinline__ uint32_t h2u(__half2 h) {
    union { __half2 h; uint32_t u; } c;
    c.h = h;
    return c.u;
}

// ---------------- W prepack (once per call; 1 block) ----------------
// idx = (kk*16 + nt)*64 + lane*2 + r ;  value = half2(W[k][n], W[k+1][n])
// k = kk*16 + r*8 + (lane&3)*2 ;  n = nt*8 + (lane>>2)
__global__ __launch_bounds__(256) void prepack_kernel(
    const float* __restrict__ W1, const float* __restrict__ W2)
{
    int tid = threadIdx.x;
    #pragma unroll
    for (int v = 0; v < 32; v++) {
        int idx   = tid + v * 256;           // 0..8191
        int r     = idx & 1;
        int lane_ = (idx >> 1) & 31;
        int nt    = (idx >> 6) & 15;
        int kk    = idx >> 10;
        int k = kk * 16 + r * 8 + (lane_ & 3) * 2;
        int n = nt * 8 + (lane_ >> 2);
        size_t o0 = (size_t)k * CH + n;
        size_t o1 = (size_t)(k + 1) * CH + n;
        g_W1p[idx] = h2u(__floats2half2_rn(__ldg(W1 + o0), __ldg(W1 + o1)));
        g_W2p[idx] = h2u(__floats2half2_rn(__ldg(W2 + o0), __ldg(W2 + o1)));
    }
}

// ---------------- degree count + graph count (fused) ----------------
__global__ void cnt_count_kernel(const int* __restrict__ dst, const int* __restrict__ batch) {
    int i = blockIdx.x * blockDim.x + threadIdx.x;
    if (i * 2 + 1 < N_EDGES_C) {
        int2 d = *(const int2*)(dst + i * 2);
        atomicAdd(&g_cnt[d.x], 1);
        atomicAdd(&g_cnt[d.y], 1);
    } else if (i * 2 < N_EDGES_C) {
        atomicAdd(&g_cnt[dst[i * 2]], 1);
    }
    if (i < N_NODES_C) atomicAdd(&g_gcnt[batch[i]], 1.0f);
}

// ---------------- single-pass decoupled-lookback scan + rowptr/cursor/dis + cnt reset ----------------
__global__ __launch_bounds__(256) void scan_lookback_kernel() {
    __shared__ int s[256];
    __shared__ int sP;
    const int b = blockIdx.x;
    const int t = threadIdx.x;
    const int i = b * 256 + t;

    int c = (i < N_NODES_C) ? g_cnt[i] : 0;
    s[t] = c;
    __syncthreads();
    for (int o = 1; o < 256; o <<= 1) {
        int u = (t >= o) ? s[t - o] : 0;
        __syncthreads();
        s[t] += u;
        __syncthreads();
    }
    const int total = s[255];

    if (b == 0) {
        if (t == 0) {
            atomicExch(&g_scan_state[0], (2ull << 32) | (unsigned)total);
            sP = 0;
        }
    } else {
        if (t == 0)
            atomicExch(&g_scan_state[b], (1ull << 32) | (unsigned)total);
        if (t < 32) {
            int lane = t;
            int P = 0;
            int j = b - 1;
            while (true) {
                int idx = j - lane;
                int flag = 0, val = 0;
                if (idx >= 0) {
                    unsigned long long v;
                    do { v = atomicAdd(&g_scan_state[idx], 0ull); flag = (int)(v >> 32); }
                    while (flag == 0);
                    val = (int)(v & 0xffffffffu);
                }
                unsigned m = __ballot_sync(0xFFFFFFFFu, (idx >= 0) && (flag == 2));
                if (m) {
                    int firstP = __ffs(m) - 1;
                    int contrib = (lane <= firstP) ? val : 0;
                    P += __reduce_add_sync(0xFFFFFFFFu, contrib);
                    break;
                } else {
                    P += __reduce_add_sync(0xFFFFFFFFu, (idx >= 0) ? val : 0);
                    j -= 32;
                }
            }
            if (lane == 0) {
                atomicExch(&g_scan_state[b], (2ull << 32) | (unsigned)(P + total));
                sP = P;
            }
        }
    }
    __syncthreads();

    if (i < N_NODES_C) {
        int pos = sP + s[t] - c;
        g_rowptr[i] = pos;
        g_cursor[i] = pos;
        g_dis[i]    = rsqrtf(1.0f + (float)c);
        g_cnt[i]    = 0;
    }
    if (b == 0 && t == 0) g_rowptr[N_NODES_C] = N_EDGES_C;
}

// ---------------- CSR fill (+ scan-state reset) ----------------
__global__ void csr_fill_kernel(const int* __restrict__ src, const int* __restrict__ dst) {
    int i = blockIdx.x * blockDim.x + threadIdx.x;
    if (i < 512) g_scan_state[i] = 0ull;
    if (i * 2 + 1 < N_EDGES_C) {
        int2 s = *(const int2*)(src + i * 2);
        int2 d = *(const int2*)(dst + i * 2);
        g_csr_src[atomicAdd(&g_cursor[d.x], 1)] = s.x;
        g_csr_src[atomicAdd(&g_cursor[d.y], 1)] = s.y;
    } else if (i * 2 < N_EDGES_C) {
        g_csr_src[atomicAdd(&g_cursor[dst[i * 2]], 1)] = src[i * 2];
    }
}

// ---------------- fp16 tensor-core GEMM: Y[r,:] = half((X[r,:] @ W) * scale[r]) ----------------
// 256 threads (8 warps), 128 rows/block, K=128 via m16n8k16, all 16 n-tiles per pass.
// X staged in smem fp16 (conflict-free); W read as pre-packed fragments from global (L1-hot).
template <typename T>
__global__ __launch_bounds__(256) void gemm_f16_kernel(
    const T* __restrict__ X, const uint32_t* __restrict__ Wp,
    __half* __restrict__ Y, const float* __restrict__ scale, int M)
{
    __shared__ __half sX[128 * SXP];         // 34816 B

    const int tid  = threadIdx.x;
    const int warp = tid >> 5;
    const int lane = tid & 31;
    const int gid  = lane >> 2;
    const int tig  = lane & 3;
    const int rowBase = blockIdx.x * 128;

    // ---- stage X tile into smem as fp16 ----
    if (sizeof(T) == 4) {                    // fp32 input (layer 1)
        const float* Xf = (const float*)X;
        #pragma unroll
        for (int v = 0; v < 16; v++) {
            int fi = tid + v * 256;          // 4096 float4
            int r  = fi >> 5;
            int c4 = (fi & 31) * 4;
            float4 val = make_float4(0.f, 0.f, 0.f, 0.f);
            int gr = rowBase + r;
            if (gr < M) val = *(const float4*)(Xf + (size_t)gr * CH + c4);
            uint32_t* p = (uint32_t*)(sX + r * SXP + c4);
            p[0] = h2u(__floats2half2_rn(val.x, val.y));
            p[1] = h2u(__floats2half2_rn(val.z, val.w));
        }
    } else {                                 // fp16 input (layer 2)
        const __half* Xh = (const __half*)X;
        #pragma unroll
        for (int v = 0; v < 8; v++) {
            int fi = tid + v * 256;          // 2048 uint4 (8 halves each)
            int r  = fi >> 4;
            int c8 = (fi & 15) * 8;
            uint4 val = make_uint4(0u, 0u, 0u, 0u);
            int gr = rowBase + r;
            if (gr < M) val = *(const uint4*)(Xh + (size_t)gr * CH + c8);
            uint32_t* p = (uint32_t*)(sX + r * SXP + c8);
            p[0] = val.x; p[1] = val.y; p[2] = val.z; p[3] = val.w;
        }
    }
    __syncthreads();

    float acc[16][4];
    #pragma unroll
    for (int nt = 0; nt < 16; nt++)
        #pragma unroll
        for (int j = 0; j < 4; j++) acc[nt][j] = 0.f;

    const int arow = warp * 16 + gid;        // this warp's A rows: arow, arow+8

    #pragma unroll
    for (int kk = 0; kk < 8; kk++) {
        // A fragments from smem (conflict-free: bank = lane identity)
        uint32_t a0 = *(const uint32_t*)(sX + arow * SXP       + kk * 16 + tig * 2);
        uint32_t a1 = *(const uint32_t*)(sX + (arow + 8) * SXP + kk * 16 + tig * 2);
        uint32_t a2 = *(const uint32_t*)(sX + arow * SXP       + kk * 16 + tig * 2 + 8);
        uint32_t a3 = *(const uint32_t*)(sX + (arow + 8) * SXP + kk * 16 + tig * 2 + 8);
        #pragma unroll
        for (int nt = 0; nt < 16; nt++) {
            uint2 b = *(const uint2*)(Wp + (size_t)(kk * 16 + nt) * 64 + lane * 2);
            float* c = acc[nt];
            asm volatile(
                "mma.sync.aligned.m16n8k16.row.col.f32.f16.f16.f32 "
                "{%0,%1,%2,%3}, {%4,%5,%6,%7}, {%8,%9}, {%0,%1,%2,%3};"
                : "+f"(c[0]), "+f"(c[1]), "+f"(c[2]), "+f"(c[3])
                : "r"(a0), "r"(a1), "r"(a2), "r"(a3), "r"(b.x), "r"(b.y));
        }
    }

    // ---- epilogue: scale rows by dis[row], convert fp16, store ----
    const int r0 = rowBase + warp * 16 + gid;
    const int r1 = r0 + 8;
    const bool v0 = (r0 < M);
    const bool v1 = (r1 < M);
    float s0 = v0 ? scale[r0] : 0.f;
    float s1 = v1 ? scale[r1] : 0.f;
    #pragma unroll
    for (int nt = 0; nt < 16; nt++) {
        int col = nt * 8 + tig * 2;
        if (v0)
            *(__half2*)(Y + (size_t)r0 * CH + col) =
                __floats2half2_rn(acc[nt][0] * s0, acc[nt][1] * s0);
        if (v1)
            *(__half2*)(Y + (size_t)r1 * CH + col) =
                __floats2half2_rn(acc[nt][2] * s1, acc[nt][3] * s1);
    }
}

// ---------------- gather aggregation (fp16 Hs rows pre-scaled by dis[row]) ----------------
__device__ __forceinline__ void acc_row(float4& acc, const __half* Hs, int srow, int lane) {
    uint2 raw = *(const uint2*)(Hs + (size_t)srow * CH + lane * 4);
    float2 f0 = __half22float2(*(__half2*)&raw.x);
    float2 f1 = __half22float2(*(__half2*)&raw.y);
    acc.x += f0.x; acc.y += f0.y; acc.z += f1.x; acc.w += f1.y;
}

template <int MODE>
__global__ __launch_bounds__(256) void agg_kernel(
    const __half* __restrict__ Hs, const float* __restrict__ bias,
    __half* __restrict__ OUT,
    const float* __restrict__ Wfc, const int* __restrict__ batch)
{
    int node = (blockIdx.x * blockDim.x + threadIdx.x) >> 5;
    int lane = threadIdx.x & 31;
    if (node >= N_NODES_C) return;

    float4 acc = make_float4(0.f, 0.f, 0.f, 0.f);
    acc_row(acc, Hs, node, lane);            // self term

    int beg = __ldg(&g_rowptr[node]);
    int end = __ldg(&g_rowptr[node + 1]);

    for (int j = beg; j < end; j += 32) {
        int n = min(32, end - j);
        int si = (lane < n) ? __ldg(&g_csr_src[j + lane]) : 0;
        int t = 0;
        for (; t + 8 <= n; t += 8) {
            int ss[8];
            #pragma unroll
            for (int k = 0; k < 8; k++) ss[k] = __shfl_sync(0xFFFFFFFFu, si, t + k);
            #pragma unroll
            for (int k = 0; k < 8; k++) acc_row(acc, Hs, ss[k], lane);
        }
        for (; t + 2 <= n; t += 2) {
            int s0 = __shfl_sync(0xFFFFFFFFu, si, t);
            int s1 = __shfl_sync(0xFFFFFFFFu, si, t + 1);
            acc_row(acc, Hs, s0, lane);
            acc_row(acc, Hs, s1, lane);
        }
        if (t < n) {
            int s0 = __shfl_sync(0xFFFFFFFFu, si, t);
            acc_row(acc, Hs, s0, lane);
        }
    }

    float dd = __ldg(&g_dis[node]);
    float4 b4 = *(const float4*)(bias + lane * 4);
    acc.x = fmaxf(acc.x * dd + b4.x, 0.f);
    acc.y = fmaxf(acc.y * dd + b4.y, 0.f);
    acc.z = fmaxf(acc.z * dd + b4.z, 0.f);
    acc.w = fmaxf(acc.w * dd + b4.w, 0.f);

    if (MODE == 0) {
        uint2 o;
        o.x = h2u(__floats2half2_rn(acc.x, acc.y));
        o.y = h2u(__floats2half2_rn(acc.z, acc.w));
        *(uint2*)(OUT + (size_t)node * CH + lane * 4) = o;
    } else {
        float4 w4 = *(const float4*)(Wfc + lane * 4);
        float s = acc.x * w4.x + acc.y * w4.y + acc.z * w4.z + acc.w * w4.w;
        #pragma unroll
        for (int o = 16; o; o >>= 1) s += __shfl_xor_sync(0xFFFFFFFFu, s, o);
        if (lane == 0) atomicAdd(&g_gsum[__ldg(batch + node)], s);
    }
}

// ---------------- final output (+ pool-state reset) ----------------
__global__ void final_out_kernel(float* __restrict__ out, const float* __restrict__ bfc) {
    int g = threadIdx.x;
    if (g < N_GRAPHS_C) {
        out[g] = g_gsum[g] / fmaxf(g_gcnt[g], 1.0f) + bfc[0];
        g_gsum[g] = 0.f;
        g_gcnt[g] = 0.f;
    }
}

// ---------------- launch (9 kernels, plain launches only) ----------------
extern "C" void kernel_launch(void* const* d_in, const int* in_sizes, int n_in,
                              void* d_out, int out_size)
{
    const float* x    = (const float*)d_in[0];
    const int*   edge = (const int*)  d_in[1];
    const int*   batch= (const int*)  d_in[2];
    const float* W1   = (const float*)d_in[3];
    const float* b1   = (const float*)d_in[4];
    const float* W2   = (const float*)d_in[5];
    const float* b2   = (const float*)d_in[6];
    const float* Wfc  = (const float*)d_in[7];
    const float* bfc  = (const float*)d_in[8];
    float* out = (float*)d_out;

    const int* srcp = edge;
    const int* dstp = edge + N_EDGES_C;

    __half *bufA = nullptr, *bufB = nullptr;
    float *disp = nullptr;
    uint32_t *w1p = nullptr, *w2p = nullptr;
    cudaGetSymbolAddress((void**)&bufA, g_bufA);
    cudaGetSymbolAddress((void**)&bufB, g_bufB);
    cudaGetSymbolAddress((void**)&disp, g_dis);
    cudaGetSymbolAddress((void**)&w1p, g_W1p);
    cudaGetSymbolAddress((void**)&w2p, g_W2p);

    const int e2grid = (N_EDGES_C / 2 + 255) / 256;
    const int agrid  = (N_NODES_C + 7) / 8;
    const int ggrid  = (N_NODES_C + 127) / 128;

    // ---- prepack W (overlaps CSR build region of the graph) ----
    prepack_kernel<<<1, 256>>>(W1, W2);

    // ---- CSR build: 3 launches ----
    cnt_count_kernel<<<e2grid, 256>>>(dstp, batch);
    scan_lookback_kernel<<<NBLK, 256>>>();
    csr_fill_kernel<<<e2grid, 256>>>(srcp, dstp);

    // ---- layer 1:  Hs = half((X@W1)*dis)  -> gather -> relu(+b1) -> fp16 ----
    gemm_f16_kernel<float><<<ggrid, 256>>>(x, w1p, bufA, disp, N_NODES_C);
    agg_kernel<0><<<agrid, 256>>>(bufA, b1, bufB, nullptr, nullptr);

    // ---- layer 2:  Hs = half((h1@W2)*dis) -> gather -> relu(+b2) -> pooled FC dot ----
    gemm_f16_kernel<__half><<<ggrid, 256>>>(bufB, w2p, bufA, disp, N_NODES_C);
    agg_kernel<1><<<agrid, 256>>>(bufA, b2, nullptr, Wfc, batch);

    // ---- final (+ reset pooling state) ----
    final_out_kernel<<<1, 256>>>(out, bfc);

    (void)in_sizes; (void)n_in; (void)out_size;
}